// round 6
// baseline (speedup 1.0000x reference)
#include <cuda_runtime.h>
#include <math.h>
#include <limits.h>

#define BB 32
#define HH 512
#define EE 512
#define VV 10000
#define FF 1280
#define PP 196
#define TT 80
#define G4 2048
#define XD 1792

// ---------------- scratch ---------------------------------------------------
__device__ float g_mean[BB * FF];
__device__ float g_h[BB * HH];
__device__ float g_c[BB * HH];
__device__ float g_hid[BB * HH];
__device__ float g_glin[BB * FF];
__device__ float g_g0a[BB * G4];
__device__ float g_g0b[BB * G4];
__device__ float g_sc[BB * PP];
__device__ float g_ctx[BB * FF];
__device__ float g_encproj[BB * PP * HH];
__device__ unsigned long long g_best[BB];

__device__ __forceinline__ float sigmoidf(float x) { return 1.0f / (1.0f + expf(-x)); }

__device__ __forceinline__ unsigned int fkey(float f) {
    unsigned int u = __float_as_uint(f);
    return (u & 0x80000000u) ? ~u : (u | 0x80000000u);
}

// ---------------------------------------------------------------------------
// GEMM tile core, 32 rows x (NC*32) cols, blockDim = 128, K % 32 == 0.
// As layout [k][row] stride 36; Ws layout [k][col] stride 66 (NC2) / 33 (NC1).
// MODE 0: W row = col0 + col (col < nvalid). MODE 1: row = (col>>3)*512 + j0 + (col&7).
// Depth-3 software pipeline: loads for chunk i+3 issued at iteration i;
// double-buffered smem, ONE __syncthreads per chunk.
// NOTE: first __syncthreads is at the TOP, before rowoff[] is read — callers
// write ro[] from a thread subset and rely on this sync for visibility.
// ---------------------------------------------------------------------------
template<int NC, int MODE>
__device__ __forceinline__ void gemm2(
    const float* __restrict__ A, const unsigned int* __restrict__ rowoff,
    const float* __restrict__ W, int ldw, int K,
    int col0, int nvalid, int j0,
    float acc[8][NC], float* As0, float* Ws0, float* As1, float* Ws1)
{
    constexpr int NWV = (NC == 2) ? 4 : 2;
    constexpr int WST = (NC == 2) ? 66 : 33;
    const int tid = threadIdx.x;
    const int tx = tid & 31, rq = tid >> 5;

    __syncthreads();   // ro[] visible to all threads; smem buffers free

    const float* ap[2];
    #pragma unroll
    for (int v = 0; v < 2; ++v) {
        int idx = tid + v * 128;
        ap[v] = A + rowoff[idx >> 3] + (idx & 7) * 4;
    }
    const float* wp[NWV]; bool wv[NWV];
    #pragma unroll
    for (int v = 0; v < NWV; ++v) {
        int idx = tid + v * 128;
        int col = idx >> 3;
        int wr;
        if (MODE == 0) { wr = col0 + col; wv[v] = (col < nvalid); }
        else           { wr = ((col >> 3) << 9) + j0 + (col & 7); wv[v] = true; }
        wp[v] = W + (size_t)wr * ldw + (idx & 7) * 4;
    }

    float* Asb[2] = {As0, As1};
    float* Wsb[2] = {Ws0, Ws1};
    const int nch = K >> 5;

    float4 ra0[2], ra1[2], rw0[NWV], rw1[NWV];

    // chunk 0 -> regs -> buf0
    #pragma unroll
    for (int v = 0; v < 2; ++v) ra0[v] = *(const float4*)(ap[v]);
    #pragma unroll
    for (int v = 0; v < NWV; ++v)
        rw0[v] = wv[v] ? *(const float4*)(wp[v]) : make_float4(0.f, 0.f, 0.f, 0.f);
    #pragma unroll
    for (int v = 0; v < 2; ++v) {
        int idx = tid + v * 128;
        int row = idx >> 3, kq = idx & 7;
        As0[(kq * 4 + 0) * 36 + row] = ra0[v].x;
        As0[(kq * 4 + 1) * 36 + row] = ra0[v].y;
        As0[(kq * 4 + 2) * 36 + row] = ra0[v].z;
        As0[(kq * 4 + 3) * 36 + row] = ra0[v].w;
    }
    #pragma unroll
    for (int v = 0; v < NWV; ++v) {
        int idx = tid + v * 128;
        int col = idx >> 3, kq = idx & 7;
        Ws0[(kq * 4 + 0) * WST + col] = rw0[v].x;
        Ws0[(kq * 4 + 1) * WST + col] = rw0[v].y;
        Ws0[(kq * 4 + 2) * WST + col] = rw0[v].z;
        Ws0[(kq * 4 + 3) * WST + col] = rw0[v].w;
    }
    // prefetch chunks 1 and 2 into regs
    if (nch > 1) {
        #pragma unroll
        for (int v = 0; v < 2; ++v) ra0[v] = *(const float4*)(ap[v] + 32);
        #pragma unroll
        for (int v = 0; v < NWV; ++v)
            rw0[v] = wv[v] ? *(const float4*)(wp[v] + 32) : make_float4(0.f, 0.f, 0.f, 0.f);
    }
    if (nch > 2) {
        #pragma unroll
        for (int v = 0; v < 2; ++v) ra1[v] = *(const float4*)(ap[v] + 64);
        #pragma unroll
        for (int v = 0; v < NWV; ++v)
            rw1[v] = wv[v] ? *(const float4*)(wp[v] + 64) : make_float4(0.f, 0.f, 0.f, 0.f);
    }
    __syncthreads();   // buf0 visible

    for (int i = 0; i < nch; ++i) {
        const int cur = i & 1;
        // store chunk i+1 into the other buffer (its last reader was iter i-1, synced)
        if (i + 1 < nch) {
            float* Asn = Asb[cur ^ 1];
            float* Wsn = Wsb[cur ^ 1];
            #pragma unroll
            for (int v = 0; v < 2; ++v) {
                int idx = tid + v * 128;
                int row = idx >> 3, kq = idx & 7;
                Asn[(kq * 4 + 0) * 36 + row] = ra0[v].x;
                Asn[(kq * 4 + 1) * 36 + row] = ra0[v].y;
                Asn[(kq * 4 + 2) * 36 + row] = ra0[v].z;
                Asn[(kq * 4 + 3) * 36 + row] = ra0[v].w;
            }
            #pragma unroll
            for (int v = 0; v < NWV; ++v) {
                int idx = tid + v * 128;
                int col = idx >> 3, kq = idx & 7;
                Wsn[(kq * 4 + 0) * WST + col] = rw0[v].x;
                Wsn[(kq * 4 + 1) * WST + col] = rw0[v].y;
                Wsn[(kq * 4 + 2) * WST + col] = rw0[v].z;
                Wsn[(kq * 4 + 3) * WST + col] = rw0[v].w;
            }
        }
        // shift regs, issue loads for chunk i+3
        #pragma unroll
        for (int v = 0; v < 2; ++v) ra0[v] = ra1[v];
        #pragma unroll
        for (int v = 0; v < NWV; ++v) rw0[v] = rw1[v];
        if (i + 3 < nch) {
            const int ko = (i + 3) * 32;
            #pragma unroll
            for (int v = 0; v < 2; ++v) ra1[v] = *(const float4*)(ap[v] + ko);
            #pragma unroll
            for (int v = 0; v < NWV; ++v)
                rw1[v] = wv[v] ? *(const float4*)(wp[v] + ko) : make_float4(0.f, 0.f, 0.f, 0.f);
        }
        // compute from buf[cur]
        const float* Asc = Asb[cur];
        const float* Wsc = Wsb[cur];
        #pragma unroll
        for (int k = 0; k < 32; ++k) {
            const float4 a0 = *(const float4*)&Asc[k * 36 + rq * 8];
            const float4 a1 = *(const float4*)&Asc[k * 36 + rq * 8 + 4];
            float av[8] = {a0.x, a0.y, a0.z, a0.w, a1.x, a1.y, a1.z, a1.w};
            if (NC == 2) {
                const float2 w2 = *(const float2*)&Wsc[k * 66 + tx * 2];
                #pragma unroll
                for (int q = 0; q < 8; ++q) {
                    acc[q][0] += av[q] * w2.x;
                    acc[q][1] += av[q] * w2.y;
                }
            } else {
                const float w = Wsc[k * 33 + tx];
                #pragma unroll
                for (int q = 0; q < 8; ++q) acc[q][0] += av[q] * w;
            }
        }
        __syncthreads();
    }
}

template<int NC>
__device__ __forceinline__ void acc_zero(float acc[8][NC]) {
    #pragma unroll
    for (int i = 0; i < 8; ++i)
        #pragma unroll
        for (int j = 0; j < NC; ++j) acc[i][j] = 0.f;
}

#define SMEM_NC2 __shared__ float As0[32*36], Ws0[32*66], As1[32*36], Ws1[32*66]; __shared__ unsigned int ro[32];
#define SMEM_NC1 __shared__ float As0[32*36], Ws0[32*33], As1[32*36], Ws1[32*33]; __shared__ unsigned int ro[32];

// ---------------------------------------------------------------------------
// setup
// ---------------------------------------------------------------------------
__global__ void k_mean(const float* __restrict__ feat) {
    int idx = blockIdx.x * 256 + threadIdx.x;
    if (blockIdx.x == 0 && threadIdx.x < BB)
        g_best[threadIdx.x] = (unsigned long long)(0xffffffffu - 1u);   // token = SOS = 1
    if (idx >= BB * FF) return;
    int b = idx / FF, f = idx % FF;
    const float* p0 = feat + (size_t)b * PP * FF + f;
    float s = 0.f;
    #pragma unroll 4
    for (int p = 0; p < PP; ++p) s += p0[(size_t)p * FF];
    g_mean[idx] = s * (1.0f / PP);
}

__global__ void k_inithc(const float* __restrict__ ihw, const float* __restrict__ ihb,
                         const float* __restrict__ icw, const float* __restrict__ icb) {
    SMEM_NC2
    float acc[8][2]; acc_zero<2>(acc);
    int bx = blockIdx.x;
    bool ish = bx < 8;
    int col0 = (ish ? bx : bx - 8) * 64;
    const float* W = ish ? ihw : icw;
    const float* bias = ish ? ihb : icb;
    float* C = ish ? g_h : g_c;
    if (threadIdx.x < 32) ro[threadIdx.x] = threadIdx.x * FF;
    gemm2<2, 0>(g_mean, ro, W, FF, FF, col0, 64, 0, acc, As0, Ws0, As1, Ws1);
    const int tx = threadIdx.x & 31, rq = threadIdx.x >> 5;
    #pragma unroll
    for (int i = 0; i < 8; ++i)
        #pragma unroll
        for (int j = 0; j < 2; ++j) {
            int c = col0 + tx * 2 + j;
            C[(rq * 8 + i) * HH + c] = acc[i][j] + bias[c];
        }
}

__global__ void k_encproj(const float* __restrict__ feat,
                          const float* __restrict__ W2_w, const float* __restrict__ W2_b) {
    SMEM_NC2
    float acc[8][2]; acc_zero<2>(acc);
    int col0 = blockIdx.x * 64;
    int m0 = blockIdx.y * 32;
    if (threadIdx.x < 32) ro[threadIdx.x] = threadIdx.x * FF;
    gemm2<2, 0>(feat + (size_t)m0 * FF, ro, W2_w, FF, FF, col0, 64, 0, acc, As0, Ws0, As1, Ws1);
    const int tx = threadIdx.x & 31, rq = threadIdx.x >> 5;
    #pragma unroll
    for (int i = 0; i < 8; ++i)
        #pragma unroll
        for (int j = 0; j < 2; ++j) {
            int c = col0 + tx * 2 + j;
            g_encproj[(size_t)(m0 + rq * 8 + i) * HH + c] = acc[i][j] + W2_b[c];
        }
}

// ---------------------------------------------------------------------------
// per-step kernels
// ---------------------------------------------------------------------------
// K1: 92 blocks.
__global__ void k_hproj(const float* __restrict__ emb,
                        const float* __restrict__ W1_w, const float* __restrict__ W1_b,
                        const float* __restrict__ gate_w, const float* __restrict__ gate_b,
                        const float* __restrict__ Whh, const float* __restrict__ Wih,
                        const float* __restrict__ bih, const float* __restrict__ bhh) {
    SMEM_NC2
    float acc[8][2]; acc_zero<2>(acc);
    const int bx = blockIdx.x;
    const int tid = threadIdx.x;
    const int tx = tid & 31, rq = tid >> 5;
    if (bx < 60) { if (tid < 32) ro[tid] = tid * HH; }
    else if (tid < 32) {
        unsigned int tok = 0xffffffffu - (unsigned int)(g_best[tid] & 0xffffffffull);
        ro[tid] = tok * EE;
    }
    if (bx < 8) {
        int col0 = bx * 64;
        gemm2<2, 0>(g_h, ro, W1_w, HH, HH, col0, 64, 0, acc, As0, Ws0, As1, Ws1);
        #pragma unroll
        for (int i = 0; i < 8; ++i)
            #pragma unroll
            for (int j = 0; j < 2; ++j) {
                int c = col0 + tx * 2 + j;
                g_hid[(rq * 8 + i) * HH + c] = acc[i][j] + W1_b[c];
            }
    } else if (bx < 28) {
        int col0 = (bx - 8) * 64;
        gemm2<2, 0>(g_h, ro, gate_w, HH, HH, col0, 64, 0, acc, As0, Ws0, As1, Ws1);
        #pragma unroll
        for (int i = 0; i < 8; ++i)
            #pragma unroll
            for (int j = 0; j < 2; ++j) {
                int c = col0 + tx * 2 + j;
                g_glin[(rq * 8 + i) * FF + c] = acc[i][j] + gate_b[c];
            }
    } else if (bx < 60) {
        int col0 = (bx - 28) * 64;
        gemm2<2, 0>(g_h, ro, Whh, HH, HH, col0, 64, 0, acc, As0, Ws0, As1, Ws1);
        #pragma unroll
        for (int i = 0; i < 8; ++i)
            #pragma unroll
            for (int j = 0; j < 2; ++j) {
                int c = col0 + tx * 2 + j;
                g_g0a[(rq * 8 + i) * G4 + c] = acc[i][j] + bih[c] + bhh[c];
            }
    } else {
        int col0 = (bx - 60) * 64;
        gemm2<2, 0>(emb, ro, Wih, XD, EE, col0, 64, 0, acc, As0, Ws0, As1, Ws1);
        #pragma unroll
        for (int i = 0; i < 8; ++i)
            #pragma unroll
            for (int j = 0; j < 2; ++j) {
                int c = col0 + tx * 2 + j;
                g_g0b[(rq * 8 + i) * G4 + c] = acc[i][j];
            }
    }
}

// K2: scores[b,p] = relu(hid[b]+encproj[b,p]).Va + Va_b  ; grid (7, 32), 256 thr
__global__ void k_scores(const float* __restrict__ Va_w, const float* __restrict__ Va_b) {
    const int b = blockIdx.y;
    const int p0 = blockIdx.x * 28;
    const int tid = threadIdx.x;
    __shared__ float4 hv[128], vv[128];
    if (tid < 128) {
        hv[tid] = ((const float4*)(g_hid + b * HH))[tid];
        vv[tid] = ((const float4*)Va_w)[tid];
    }
    __syncthreads();
    const int wid = tid >> 5, ln = tid & 31;
    const float vb = Va_b[0];
    for (int p = p0 + wid; p < p0 + 28; p += 8) {
        const float4* ep = (const float4*)(g_encproj + ((size_t)b * PP + p) * HH);
        float s = 0.f;
        #pragma unroll
        for (int u = 0; u < 4; ++u) {
            const float4 e = ep[ln + 32 * u];
            const float4 h = hv[ln + 32 * u];
            const float4 va = vv[ln + 32 * u];
            float t;
            t = h.x + e.x; if (t > 0.f) s += t * va.x;
            t = h.y + e.y; if (t > 0.f) s += t * va.y;
            t = h.z + e.z; if (t > 0.f) s += t * va.z;
            t = h.w + e.w; if (t > 0.f) s += t * va.w;
        }
        #pragma unroll
        for (int off = 16; off; off >>= 1) s += __shfl_xor_sync(0xffffffffu, s, off);
        if (ln == 0) g_sc[b * PP + p] = s + vb;
    }
}

// K3: softmax -> weights; context = w^T @ feat (4-way p-split); * sigmoid(glin)
__global__ void k_ctx(const float* __restrict__ feat, float* __restrict__ attn_t) {
    const int bx = blockIdx.x;                     // 320
    const int b = bx / 10, f0 = (bx % 10) * 128;
    const int tid = threadIdx.x;                   // 512
    __shared__ float ws[PP];
    __shared__ float red[512];
    __shared__ float part[4][128];
    float v = (tid < PP) ? g_sc[b * PP + tid] : -INFINITY;
    red[tid] = v; __syncthreads();
    for (int st = 256; st > 0; st >>= 1) { if (tid < st) red[tid] = fmaxf(red[tid], red[tid + st]); __syncthreads(); }
    const float mx = red[0];
    __syncthreads();
    float e = (tid < PP) ? expf(v - mx) : 0.f;
    red[tid] = e; __syncthreads();
    for (int st = 256; st > 0; st >>= 1) { if (tid < st) red[tid] += red[tid + st]; __syncthreads(); }
    const float inv = 1.0f / red[0];
    if (tid < PP) {
        float w = e * inv;
        ws[tid] = w;
        if (f0 == 0) attn_t[(size_t)b * TT * PP + tid] = w;
    }
    __syncthreads();
    const int fl = tid & 127, pc = tid >> 7;
    const float* fb = feat + (size_t)b * PP * FF + f0 + fl;
    const int ps = pc * 49;
    float acc = 0.f;
    #pragma unroll 7
    for (int p = ps; p < ps + 49; ++p) acc += ws[p] * fb[(size_t)p * FF];
    part[pc][fl] = acc;
    __syncthreads();
    if (tid < 128) {
        float a = part[0][tid] + part[1][tid] + part[2][tid] + part[3][tid];
        g_ctx[b * FF + f0 + tid] = a * sigmoidf(g_glin[b * FF + f0 + tid]);
    }
}

// K4: gates = ctx@WihF^T + g0a + g0b, LSTM elementwise. 64 blocks, j0 = bx*8.
__global__ void k_gates_lstm(const float* __restrict__ Wih) {
    SMEM_NC1
    __shared__ float gs[32 * 32];
    float acc[8][1]; acc_zero<1>(acc);
    const int bx = blockIdx.x;
    const int tid = threadIdx.x;
    const int j0 = bx * 8;
    if (tid < 32) ro[tid] = tid * FF;
    gemm2<1, 1>(g_ctx, ro, Wih + EE, XD, FF, 0, 32, j0, acc, As0, Ws0, As1, Ws1);
    const int tx = tid & 31, rq = tid >> 5;
    {
        const int g = tx >> 3, jj = tx & 7;
        const int ac = (g << 9) + j0 + jj;
        #pragma unroll
        for (int i = 0; i < 8; ++i) {
            int r = rq * 8 + i;
            gs[r * 32 + tx] = acc[i][0] + g_g0a[r * G4 + ac] + g_g0b[r * G4 + ac];
        }
    }
    if (bx == 0 && tid < 32) g_best[tid] = 0ull;   // reset argmax accumulator for K5
    __syncthreads();
    #pragma unroll
    for (int s = 0; s < 2; ++s) {
        int q = tid + s * 128;
        int r = q >> 3, jj = q & 7;
        float ig = sigmoidf(gs[r * 32 + jj]);
        float fg = sigmoidf(gs[r * 32 + 8 + jj]);
        float gg = tanhf(gs[r * 32 + 16 + jj]);
        float og = sigmoidf(gs[r * 32 + 24 + jj]);
        int idx = r * HH + j0 + jj;
        float c = fg * g_c[idx] + ig * gg;
        g_c[idx] = c;
        g_h[idx] = og * tanhf(c);
    }
}

// K5: logits + fused argmax. 313 blocks, 32 cols each.
__global__ void k_logits(const float* __restrict__ out_w, const float* __restrict__ out_b,
                         float* __restrict__ dec_t) {
    SMEM_NC1
    float acc[8][1]; acc_zero<1>(acc);
    const int bx = blockIdx.x;
    const int col0 = bx * 32;
    const int nvalid = min(32, VV - col0);
    const int tid = threadIdx.x;
    if (tid < 32) ro[tid] = tid * HH;
    gemm2<1, 0>(g_h, ro, out_w, HH, HH, col0, nvalid, 0, acc, As0, Ws0, As1, Ws1);
    const int tx = tid & 31, rq = tid >> 5;
    const bool val = (tx < nvalid);
    const int c = col0 + tx;
    const float ob = val ? out_b[c] : 0.f;
    #pragma unroll
    for (int i = 0; i < 8; ++i) {
        const int r = rq * 8 + i;
        unsigned long long pk = 0ull;
        if (val) {
            float vv = acc[i][0] + ob;
            dec_t[(size_t)r * TT * VV + c] = vv;
            pk = ((unsigned long long)fkey(vv) << 32) | (0xffffffffu - (unsigned int)c);
        }
        #pragma unroll
        for (int off = 16; off; off >>= 1) {
            unsigned long long o = __shfl_xor_sync(0xffffffffu, pk, off);
            if (o > pk) pk = o;
        }
        if (tx == 0) atomicMax(&g_best[r], pk);
    }
}

__global__ void k_copyhc(float* __restrict__ hout, float* __restrict__ cout) {
    int idx = blockIdx.x * 256 + threadIdx.x;
    if (idx < BB * HH) hout[idx] = g_h[idx];
    else if (idx < 2 * BB * HH) cout[idx - BB * HH] = g_c[idx - BB * HH];
}

// ---------------------------------------------------------------------------
extern "C" void kernel_launch(void* const* d_in, const int* in_sizes, int n_in,
                              void* d_out, int out_size) {
    const float* feat   = (const float*)d_in[0];
    const float* emb    = (const float*)d_in[3];
    const float* W1_w   = (const float*)d_in[4];
    const float* W1_b   = (const float*)d_in[5];
    const float* W2_w   = (const float*)d_in[6];
    const float* W2_b   = (const float*)d_in[7];
    const float* Va_w   = (const float*)d_in[8];
    const float* Va_b   = (const float*)d_in[9];
    const float* Wih    = (const float*)d_in[10];
    const float* Whh    = (const float*)d_in[11];
    const float* bih    = (const float*)d_in[12];
    const float* bhh    = (const float*)d_in[13];
    const float* out_w  = (const float*)d_in[14];
    const float* out_b  = (const float*)d_in[15];
    const float* ihw    = (const float*)d_in[16];
    const float* ihb    = (const float*)d_in[17];
    const float* icw    = (const float*)d_in[18];
    const float* icb    = (const float*)d_in[19];
    const float* gate_w = (const float*)d_in[20];
    const float* gate_b = (const float*)d_in[21];

    float* out  = (float*)d_out;
    float* dec  = out;                                   // [B, T, V]
    float* hout = out + (size_t)BB * TT * VV;            // [B, H]
    float* cout = hout + (size_t)BB * HH;                // [B, H]
    float* attn = cout + (size_t)BB * HH;                // [B, T, P]

    k_mean<<<160, 256>>>(feat);
    k_inithc<<<16, 128>>>(ihw, ihb, icw, icb);
    k_encproj<<<dim3(8, 196), 128>>>(feat, W2_w, W2_b);

    for (int t = 0; t < TT; ++t) {
        k_hproj<<<92, 128>>>(emb, W1_w, W1_b, gate_w, gate_b, Whh, Wih, bih, bhh);
        k_scores<<<dim3(7, 32), 256>>>(Va_w, Va_b);
        k_ctx<<<320, 512>>>(feat, attn + (size_t)t * PP);
        k_gates_lstm<<<64, 128>>>(Wih);
        k_logits<<<313, 128>>>(out_w, out_b, dec + (size_t)t * VV);
    }
    k_copyhc<<<128, 256>>>(hout, cout);
}

// round 7
// speedup vs baseline: 1.7372x; 1.7372x over previous
#include <cuda_runtime.h>
#include <math.h>
#include <limits.h>

#define BB 32
#define HH 512
#define EE 512
#define VV 10000
#define FF 1280
#define PP 196
#define TT 80
#define G4 2048
#define XD 1792

// ---------------- scratch ---------------------------------------------------
__device__ float g_mean[BB * FF];
__device__ float g_h[BB * HH];
__device__ float g_c[BB * HH];
__device__ float g_hid4[4][BB * HH];     // W1 partials (K quarters)
__device__ float g_glin4[4][BB * FF];    // gate partials
__device__ float g_g04[8][BB * G4];      // [0..3]=Whh quarters, [4..7]=WihE quarters
__device__ float g_gtp4[4][BB * G4];     // ctx@WihF quarters
__device__ float g_sc[BB * PP];
__device__ float g_ctx[BB * FF];
__device__ float g_encproj[BB * PP * HH];
__device__ unsigned long long g_best[BB];

__device__ __forceinline__ float sigmoidf(float x) { return 1.0f / (1.0f + expf(-x)); }

__device__ __forceinline__ unsigned int fkey(float f) {
    unsigned int u = __float_as_uint(f);
    return (u & 0x80000000u) ? ~u : (u | 0x80000000u);
}

// ---------------------------------------------------------------------------
// GEMM tile core (R4 style), 32 rows x (NC*32) cols, blockDim = 128, K%32==0.
// As layout [k][row] stride 36 (broadcast LDS.128); Ws [k][col] stride 66/33.
// MODE 0: W row = col0 + col (col < nvalid). MODE 1: row = (col>>3)*512 + j0 + (col&7).
// Register double-buffer, single smem buffer, 2 syncs/chunk.
// First __syncthreads at TOP: makes caller-written ro[] visible before use.
// ---------------------------------------------------------------------------
template<int NC, int MODE>
__device__ __forceinline__ void gemm2(
    const float* __restrict__ A, const unsigned int* __restrict__ rowoff,
    const float* __restrict__ W, int ldw, int K,
    int col0, int nvalid, int j0,
    float acc[8][NC], float* As, float* Ws)
{
    constexpr int NWV = (NC == 2) ? 4 : 2;
    constexpr int WST = (NC == 2) ? 66 : 33;
    const int tid = threadIdx.x;
    const int tx = tid & 31, rq = tid >> 5;

    __syncthreads();   // ro[] visible; smem buffers free

    const float* ap[2];
    #pragma unroll
    for (int v = 0; v < 2; ++v) {
        int idx = tid + v * 128;
        ap[v] = A + rowoff[idx >> 3] + (idx & 7) * 4;
    }
    const float* wp[NWV]; bool wv[NWV];
    #pragma unroll
    for (int v = 0; v < NWV; ++v) {
        int idx = tid + v * 128;
        int col = idx >> 3;
        int wr;
        if (MODE == 0) { wr = col0 + col; wv[v] = (col < nvalid); }
        else           { wr = ((col >> 3) << 9) + j0 + (col & 7); wv[v] = true; }
        wp[v] = W + (size_t)wr * ldw + (idx & 7) * 4;
    }

    float4 ra[2], rw[NWV];
    #pragma unroll
    for (int v = 0; v < 2; ++v) ra[v] = *(const float4*)(ap[v]);
    #pragma unroll
    for (int v = 0; v < NWV; ++v)
        rw[v] = wv[v] ? *(const float4*)(wp[v]) : make_float4(0.f, 0.f, 0.f, 0.f);

    for (int k0 = 0; k0 < K; k0 += 32) {
        #pragma unroll
        for (int v = 0; v < 2; ++v) {
            int idx = tid + v * 128;
            int row = idx >> 3, kq = idx & 7;
            As[(kq * 4 + 0) * 36 + row] = ra[v].x;
            As[(kq * 4 + 1) * 36 + row] = ra[v].y;
            As[(kq * 4 + 2) * 36 + row] = ra[v].z;
            As[(kq * 4 + 3) * 36 + row] = ra[v].w;
        }
        #pragma unroll
        for (int v = 0; v < NWV; ++v) {
            int idx = tid + v * 128;
            int col = idx >> 3, kq = idx & 7;
            Ws[(kq * 4 + 0) * WST + col] = rw[v].x;
            Ws[(kq * 4 + 1) * WST + col] = rw[v].y;
            Ws[(kq * 4 + 2) * WST + col] = rw[v].z;
            Ws[(kq * 4 + 3) * WST + col] = rw[v].w;
        }
        __syncthreads();
        const int kn = k0 + 32;
        if (kn < K) {
            #pragma unroll
            for (int v = 0; v < 2; ++v) ra[v] = *(const float4*)(ap[v] + kn);
            #pragma unroll
            for (int v = 0; v < NWV; ++v)
                rw[v] = wv[v] ? *(const float4*)(wp[v] + kn) : make_float4(0.f, 0.f, 0.f, 0.f);
        }
        #pragma unroll
        for (int k = 0; k < 32; ++k) {
            const float4 a0 = *(const float4*)&As[k * 36 + rq * 8];
            const float4 a1 = *(const float4*)&As[k * 36 + rq * 8 + 4];
            float av[8] = {a0.x, a0.y, a0.z, a0.w, a1.x, a1.y, a1.z, a1.w};
            if (NC == 2) {
                const float2 w2 = *(const float2*)&Ws[k * 66 + tx * 2];
                #pragma unroll
                for (int q = 0; q < 8; ++q) {
                    acc[q][0] += av[q] * w2.x;
                    acc[q][1] += av[q] * w2.y;
                }
            } else {
                const float w = Ws[k * 33 + tx];
                #pragma unroll
                for (int q = 0; q < 8; ++q) acc[q][0] += av[q] * w;
            }
        }
        __syncthreads();
    }
}

template<int NC>
__device__ __forceinline__ void acc_zero(float acc[8][NC]) {
    #pragma unroll
    for (int i = 0; i < 8; ++i)
        #pragma unroll
        for (int j = 0; j < NC; ++j) acc[i][j] = 0.f;
}

#define SMEM_NC2 __shared__ float As[32*36], Ws[32*66]; __shared__ unsigned int ro[32];
#define SMEM_NC1 __shared__ float As[32*36], Ws[32*33]; __shared__ unsigned int ro[32];

// ---------------------------------------------------------------------------
// setup
// ---------------------------------------------------------------------------
__global__ void k_mean(const float* __restrict__ feat) {
    int idx = blockIdx.x * 256 + threadIdx.x;
    if (blockIdx.x == 0 && threadIdx.x < BB)
        g_best[threadIdx.x] = (unsigned long long)(0xffffffffu - 1u);   // token = SOS = 1
    if (idx >= BB * FF) return;
    int b = idx / FF, f = idx % FF;
    const float* p0 = feat + (size_t)b * PP * FF + f;
    float s = 0.f;
    #pragma unroll 4
    for (int p = 0; p < PP; ++p) s += p0[(size_t)p * FF];
    g_mean[idx] = s * (1.0f / PP);
}

__global__ void k_inithc(const float* __restrict__ ihw, const float* __restrict__ ihb,
                         const float* __restrict__ icw, const float* __restrict__ icb) {
    SMEM_NC2
    float acc[8][2]; acc_zero<2>(acc);
    int bx = blockIdx.x;
    bool ish = bx < 8;
    int col0 = (ish ? bx : bx - 8) * 64;
    const float* W = ish ? ihw : icw;
    const float* bias = ish ? ihb : icb;
    float* C = ish ? g_h : g_c;
    if (threadIdx.x < 32) ro[threadIdx.x] = threadIdx.x * FF;
    gemm2<2, 0>(g_mean, ro, W, FF, FF, col0, 64, 0, acc, As, Ws);
    const int tx = threadIdx.x & 31, rq = threadIdx.x >> 5;
    #pragma unroll
    for (int i = 0; i < 8; ++i)
        #pragma unroll
        for (int j = 0; j < 2; ++j) {
            int c = col0 + tx * 2 + j;
            C[(rq * 8 + i) * HH + c] = acc[i][j] + bias[c];
        }
}

__global__ void k_encproj(const float* __restrict__ feat,
                          const float* __restrict__ W2_w, const float* __restrict__ W2_b) {
    SMEM_NC2
    float acc[8][2]; acc_zero<2>(acc);
    int col0 = blockIdx.x * 64;
    int m0 = blockIdx.y * 32;
    if (threadIdx.x < 32) ro[threadIdx.x] = threadIdx.x * FF;
    gemm2<2, 0>(feat + (size_t)m0 * FF, ro, W2_w, FF, FF, col0, 64, 0, acc, As, Ws);
    const int tx = threadIdx.x & 31, rq = threadIdx.x >> 5;
    #pragma unroll
    for (int i = 0; i < 8; ++i)
        #pragma unroll
        for (int j = 0; j < 2; ++j) {
            int c = col0 + tx * 2 + j;
            g_encproj[(size_t)(m0 + rq * 8 + i) * HH + c] = acc[i][j] + W2_b[c];
        }
}

// ---------------------------------------------------------------------------
// per-step kernels
// ---------------------------------------------------------------------------
// K1: 368 blocks = 4 K-quarters x 92 col-tiles.  q = bx&3 selects K range q*128.
__global__ void k_hproj(const float* __restrict__ emb,
                        const float* __restrict__ W1_w, const float* __restrict__ W1_b,
                        const float* __restrict__ gate_w, const float* __restrict__ gate_b,
                        const float* __restrict__ Whh, const float* __restrict__ Wih,
                        const float* __restrict__ bih, const float* __restrict__ bhh) {
    SMEM_NC2
    float acc[8][2]; acc_zero<2>(acc);
    const int bx = blockIdx.x;
    const int q = bx & 3, u = bx >> 2;          // q: K quarter, u: 0..91 col-tile pattern
    const int koff = q * 128;
    const int tid = threadIdx.x;
    const int tx = tid & 31, rq = tid >> 5;
    if (u < 60) { if (tid < 32) ro[tid] = tid * HH; }
    else if (tid < 32) {
        unsigned int tok = 0xffffffffu - (unsigned int)(g_best[tid] & 0xffffffffull);
        ro[tid] = tok * EE;
    }
    if (u < 8) {
        int col0 = u * 64;
        gemm2<2, 0>(g_h + koff, ro, W1_w + koff, HH, 128, col0, 64, 0, acc, As, Ws);
        #pragma unroll
        for (int i = 0; i < 8; ++i)
            #pragma unroll
            for (int j = 0; j < 2; ++j) {
                int c = col0 + tx * 2 + j;
                g_hid4[q][(rq * 8 + i) * HH + c] = acc[i][j] + (q == 0 ? W1_b[c] : 0.f);
            }
    } else if (u < 28) {
        int col0 = (u - 8) * 64;
        gemm2<2, 0>(g_h + koff, ro, gate_w + koff, HH, 128, col0, 64, 0, acc, As, Ws);
        #pragma unroll
        for (int i = 0; i < 8; ++i)
            #pragma unroll
            for (int j = 0; j < 2; ++j) {
                int c = col0 + tx * 2 + j;
                g_glin4[q][(rq * 8 + i) * FF + c] = acc[i][j] + (q == 0 ? gate_b[c] : 0.f);
            }
    } else if (u < 60) {
        int col0 = (u - 28) * 64;
        gemm2<2, 0>(g_h + koff, ro, Whh + koff, HH, 128, col0, 64, 0, acc, As, Ws);
        #pragma unroll
        for (int i = 0; i < 8; ++i)
            #pragma unroll
            for (int j = 0; j < 2; ++j) {
                int c = col0 + tx * 2 + j;
                g_g04[q][(rq * 8 + i) * G4 + c] = acc[i][j] + (q == 0 ? bih[c] + bhh[c] : 0.f);
            }
    } else {
        int col0 = (u - 60) * 64;
        gemm2<2, 0>(emb + koff, ro, Wih + koff, XD, 128, col0, 64, 0, acc, As, Ws);
        #pragma unroll
        for (int i = 0; i < 8; ++i)
            #pragma unroll
            for (int j = 0; j < 2; ++j) {
                int c = col0 + tx * 2 + j;
                g_g04[4 + q][(rq * 8 + i) * G4 + c] = acc[i][j];
            }
    }
}

// K2: scores[b,p] = relu(hid[b]+encproj[b,p]).Va + Va_b ; grid (7, 32), 256 thr
__global__ void k_scores(const float* __restrict__ Va_w, const float* __restrict__ Va_b) {
    const int b = blockIdx.y;
    const int p0 = blockIdx.x * 28;
    const int tid = threadIdx.x;
    __shared__ float4 hv[128], vv[128];
    if (tid < 128) {
        float4 s0 = ((const float4*)(g_hid4[0] + b * HH))[tid];
        float4 s1 = ((const float4*)(g_hid4[1] + b * HH))[tid];
        float4 s2 = ((const float4*)(g_hid4[2] + b * HH))[tid];
        float4 s3 = ((const float4*)(g_hid4[3] + b * HH))[tid];
        hv[tid] = make_float4(s0.x + s1.x + s2.x + s3.x, s0.y + s1.y + s2.y + s3.y,
                              s0.z + s1.z + s2.z + s3.z, s0.w + s1.w + s2.w + s3.w);
        vv[tid] = ((const float4*)Va_w)[tid];
    }
    __syncthreads();
    const int wid = tid >> 5, ln = tid & 31;
    const float vb = Va_b[0];
    for (int p = p0 + wid; p < p0 + 28; p += 8) {
        const float4* ep = (const float4*)(g_encproj + ((size_t)b * PP + p) * HH);
        float s = 0.f;
        #pragma unroll
        for (int u = 0; u < 4; ++u) {
            const float4 e = ep[ln + 32 * u];
            const float4 h = hv[ln + 32 * u];
            const float4 va = vv[ln + 32 * u];
            float t;
            t = h.x + e.x; if (t > 0.f) s += t * va.x;
            t = h.y + e.y; if (t > 0.f) s += t * va.y;
            t = h.z + e.z; if (t > 0.f) s += t * va.z;
            t = h.w + e.w; if (t > 0.f) s += t * va.w;
        }
        #pragma unroll
        for (int off = 16; off; off >>= 1) s += __shfl_xor_sync(0xffffffffu, s, off);
        if (ln == 0) g_sc[b * PP + p] = s + vb;
    }
}

// K3: softmax -> weights; context = w^T @ feat (4-way p-split); * sigmoid(glin)
__global__ void k_ctx(const float* __restrict__ feat, float* __restrict__ attn_t) {
    const int bx = blockIdx.x;                     // 320
    const int b = bx / 10, f0 = (bx % 10) * 128;
    const int tid = threadIdx.x;                   // 512
    __shared__ float ws[PP];
    __shared__ float red[512];
    __shared__ float part[4][128];
    float v = (tid < PP) ? g_sc[b * PP + tid] : -INFINITY;
    red[tid] = v; __syncthreads();
    for (int st = 256; st > 0; st >>= 1) { if (tid < st) red[tid] = fmaxf(red[tid], red[tid + st]); __syncthreads(); }
    const float mx = red[0];
    __syncthreads();
    float e = (tid < PP) ? expf(v - mx) : 0.f;
    red[tid] = e; __syncthreads();
    for (int st = 256; st > 0; st >>= 1) { if (tid < st) red[tid] += red[tid + st]; __syncthreads(); }
    const float inv = 1.0f / red[0];
    if (tid < PP) {
        float w = e * inv;
        ws[tid] = w;
        if (f0 == 0) attn_t[(size_t)b * TT * PP + tid] = w;
    }
    __syncthreads();
    const int fl = tid & 127, pc = tid >> 7;
    const float* fb = feat + (size_t)b * PP * FF + f0 + fl;
    const int ps = pc * 49;
    float acc = 0.f;
    #pragma unroll 7
    for (int p = ps; p < ps + 49; ++p) acc += ws[p] * fb[(size_t)p * FF];
    part[pc][fl] = acc;
    __syncthreads();
    if (tid < 128) {
        const int fi = b * FF + f0 + tid;
        float gl = g_glin4[0][fi] + g_glin4[1][fi] + g_glin4[2][fi] + g_glin4[3][fi];
        float a = part[0][tid] + part[1][tid] + part[2][tid] + part[3][tid];
        g_ctx[b * FF + f0 + tid] = a * sigmoidf(gl);
    }
}

// K4: gtp[q] = ctx[:, q*320:(q+1)*320] @ WihF[:, same]^T. 256 blocks = 4q x 64 tiles.
__global__ void k_gates(const float* __restrict__ Wih) {
    SMEM_NC1
    float acc[8][1]; acc_zero<1>(acc);
    const int bx = blockIdx.x;
    const int q = bx & 3, u = bx >> 2;             // u: 0..63, j0 = u*8
    const int koff = q * 320;
    const int tid = threadIdx.x;
    const int j0 = u * 8;
    if (tid < 32) ro[tid] = tid * FF;
    gemm2<1, 1>(g_ctx + koff, ro, Wih + EE + koff, XD, 320, 0, 32, j0, acc, As, Ws);
    const int tx = tid & 31, rq = tid >> 5;
    const int g = tx >> 3, jj = tx & 7;
    const int ac = (g << 9) + j0 + jj;
    #pragma unroll
    for (int i = 0; i < 8; ++i) {
        int r = rq * 8 + i;
        g_gtp4[q][r * G4 + ac] = acc[i][0];
    }
}

// K4b: sum 12 partials per gate element, LSTM elementwise, reset g_best. 64x256.
__global__ void k_lstm() {
    const int idx = blockIdx.x * 256 + threadIdx.x;    // 0..16383 (b, j)
    if (blockIdx.x == 0 && threadIdx.x < 32) g_best[threadIdx.x] = 0ull;
    const int b = idx >> 9, j = idx & 511;
    float gv[4];
    #pragma unroll
    for (int g = 0; g < 4; ++g) {
        const int c = b * G4 + (g << 9) + j;
        float s = 0.f;
        #pragma unroll
        for (int q = 0; q < 4; ++q)
            s += g_g04[q][c] + g_g04[4 + q][c] + g_gtp4[q][c];
        gv[g] = s;
    }
    float ig = sigmoidf(gv[0]);
    float fg = sigmoidf(gv[1]);
    float gg = tanhf(gv[2]);
    float og = sigmoidf(gv[3]);
    float c = fg * g_c[idx] + ig * gg;
    g_c[idx] = c;
    g_h[idx] = og * tanhf(c);
}

// K5: logits + fused argmax. 313 blocks, 32 cols each.
__global__ void k_logits(const float* __restrict__ out_w, const float* __restrict__ out_b,
                         float* __restrict__ dec_t) {
    SMEM_NC1
    float acc[8][1]; acc_zero<1>(acc);
    const int bx = blockIdx.x;
    const int col0 = bx * 32;
    const int nvalid = min(32, VV - col0);
    const int tid = threadIdx.x;
    if (tid < 32) ro[tid] = tid * HH;
    gemm2<1, 0>(g_h, ro, out_w, HH, HH, col0, nvalid, 0, acc, As, Ws);
    const int tx = tid & 31, rq = tid >> 5;
    const bool val = (tx < nvalid);
    const int c = col0 + tx;
    const float ob = val ? out_b[c] : 0.f;
    #pragma unroll
    for (int i = 0; i < 8; ++i) {
        const int r = rq * 8 + i;
        unsigned long long pk = 0ull;
        if (val) {
            float vv = acc[i][0] + ob;
            dec_t[(size_t)r * TT * VV + c] = vv;
            pk = ((unsigned long long)fkey(vv) << 32) | (0xffffffffu - (unsigned int)c);
        }
        #pragma unroll
        for (int off = 16; off; off >>= 1) {
            unsigned long long o = __shfl_xor_sync(0xffffffffu, pk, off);
            if (o > pk) pk = o;
        }
        if (tx == 0) atomicMax(&g_best[r], pk);
    }
}

__global__ void k_copyhc(float* __restrict__ hout, float* __restrict__ cout) {
    int idx = blockIdx.x * 256 + threadIdx.x;
    if (idx < BB * HH) hout[idx] = g_h[idx];
    else if (idx < 2 * BB * HH) cout[idx - BB * HH] = g_c[idx - BB * HH];
}

// ---------------------------------------------------------------------------
extern "C" void kernel_launch(void* const* d_in, const int* in_sizes, int n_in,
                              void* d_out, int out_size) {
    const float* feat   = (const float*)d_in[0];
    const float* emb    = (const float*)d_in[3];
    const float* W1_w   = (const float*)d_in[4];
    const float* W1_b   = (const float*)d_in[5];
    const float* W2_w   = (const float*)d_in[6];
    const float* W2_b   = (const float*)d_in[7];
    const float* Va_w   = (const float*)d_in[8];
    const float* Va_b   = (const float*)d_in[9];
    const float* Wih    = (const float*)d_in[10];
    const float* Whh    = (const float*)d_in[11];
    const float* bih    = (const float*)d_in[12];
    const float* bhh    = (const float*)d_in[13];
    const float* out_w  = (const float*)d_in[14];
    const float* out_b  = (const float*)d_in[15];
    const float* ihw    = (const float*)d_in[16];
    const float* ihb    = (const float*)d_in[17];
    const float* icw    = (const float*)d_in[18];
    const float* icb    = (const float*)d_in[19];
    const float* gate_w = (const float*)d_in[20];
    const float* gate_b = (const float*)d_in[21];

    float* out  = (float*)d_out;
    float* dec  = out;                                   // [B, T, V]
    float* hout = out + (size_t)BB * TT * VV;            // [B, H]
    float* cout = hout + (size_t)BB * HH;                // [B, H]
    float* attn = cout + (size_t)BB * HH;                // [B, T, P]

    k_mean<<<160, 256>>>(feat);
    k_inithc<<<16, 128>>>(ihw, ihb, icw, icb);
    k_encproj<<<dim3(8, 196), 128>>>(feat, W2_w, W2_b);

    for (int t = 0; t < TT; ++t) {
        k_hproj<<<368, 128>>>(emb, W1_w, W1_b, gate_w, gate_b, Whh, Wih, bih, bhh);
        k_scores<<<dim3(7, 32), 256>>>(Va_w, Va_b);
        k_ctx<<<320, 512>>>(feat, attn + (size_t)t * PP);
        k_gates<<<256, 128>>>(Wih);
        k_lstm<<<64, 256>>>();
        k_logits<<<313, 128>>>(out_w, out_b, dec + (size_t)t * VV);
    }
    k_copyhc<<<128, 256>>>(hout, cout);
}

// round 9
// speedup vs baseline: 1.7784x; 1.0237x over previous
#include <cuda_runtime.h>
#include <math.h>
#include <limits.h>

#define BB 32
#define HH 512
#define EE 512
#define VV 10000
#define FF 1280
#define PP 196
#define TT 80
#define G4 2048
#define XD 1792

// ---------------- scratch ---------------------------------------------------
__device__ float g_mean[BB * FF];
__device__ float g_h[BB * HH];
__device__ float g_c[BB * HH];
__device__ float g_hid4[4][BB * HH];     // W1 partials (K quarters)
__device__ float g_glin4[4][BB * FF];    // gate partials
__device__ float g_g04[8][BB * G4];      // [0..3]=Whh quarters, [4..7]=WihE quarters
__device__ float g_gtp4[4][BB * G4];     // ctx@WihF quarters
__device__ float g_sc[BB * PP];
__device__ float g_ctx[BB * FF];
__device__ float g_encproj[BB * PP * HH];
__device__ unsigned long long g_best[BB];

__device__ __forceinline__ float sigmoidf(float x) { return 1.0f / (1.0f + expf(-x)); }

__device__ __forceinline__ unsigned int fkey(float f) {
    unsigned int u = __float_as_uint(f);
    return (u & 0x80000000u) ? ~u : (u | 0x80000000u);
}

// ---------------------------------------------------------------------------
// 128-lane GEMM tile core (one K-group of a 256-thread block, or standalone).
// 32 rows x (NC*32) cols, K % 32 == 0. t = lane id within the group (0..127).
// As layout [k][row] stride 36; Ws [k][col] stride 66/33.
// MODE 0: W row = col0 + col (col < nvalid). MODE 1: row = (col>>3)*512+j0+(col&7).
// First __syncthreads at TOP (whole block): caller-written ro[] visibility.
// All groups in the block must call with the SAME K (matched barriers).
// ---------------------------------------------------------------------------
template<int NC, int MODE>
__device__ __forceinline__ void gemm_core(
    int t,
    const float* __restrict__ A, const unsigned int* __restrict__ rowoff,
    const float* __restrict__ W, int ldw, int K,
    int col0, int nvalid, int j0,
    float acc[8][NC], float* As, float* Ws)
{
    constexpr int NWV = (NC == 2) ? 4 : 2;
    constexpr int WST = (NC == 2) ? 66 : 33;
    const int tx = t & 31, rq = t >> 5;

    __syncthreads();   // ro[] visible; smem buffers free

    const float* ap[2];
    #pragma unroll
    for (int v = 0; v < 2; ++v) {
        int idx = t + v * 128;
        ap[v] = A + rowoff[idx >> 3] + (idx & 7) * 4;
    }
    const float* wp[NWV]; bool wv[NWV];
    #pragma unroll
    for (int v = 0; v < NWV; ++v) {
        int idx = t + v * 128;
        int col = idx >> 3;
        int wr;
        if (MODE == 0) { wr = col0 + col; wv[v] = (col < nvalid); }
        else           { wr = ((col >> 3) << 9) + j0 + (col & 7); wv[v] = true; }
        wp[v] = W + (size_t)wr * ldw + (idx & 7) * 4;
    }

    float4 ra[2], rw[NWV];
    #pragma unroll
    for (int v = 0; v < 2; ++v) ra[v] = *(const float4*)(ap[v]);
    #pragma unroll
    for (int v = 0; v < NWV; ++v)
        rw[v] = wv[v] ? *(const float4*)(wp[v]) : make_float4(0.f, 0.f, 0.f, 0.f);

    for (int k0 = 0; k0 < K; k0 += 32) {
        #pragma unroll
        for (int v = 0; v < 2; ++v) {
            int idx = t + v * 128;
            int row = idx >> 3, kq = idx & 7;
            As[(kq * 4 + 0) * 36 + row] = ra[v].x;
            As[(kq * 4 + 1) * 36 + row] = ra[v].y;
            As[(kq * 4 + 2) * 36 + row] = ra[v].z;
            As[(kq * 4 + 3) * 36 + row] = ra[v].w;
        }
        #pragma unroll
        for (int v = 0; v < NWV; ++v) {
            int idx = t + v * 128;
            int col = idx >> 3, kq = idx & 7;
            Ws[(kq * 4 + 0) * WST + col] = rw[v].x;
            Ws[(kq * 4 + 1) * WST + col] = rw[v].y;
            Ws[(kq * 4 + 2) * WST + col] = rw[v].z;
            Ws[(kq * 4 + 3) * WST + col] = rw[v].w;
        }
        __syncthreads();
        const int kn = k0 + 32;
        if (kn < K) {
            #pragma unroll
            for (int v = 0; v < 2; ++v) ra[v] = *(const float4*)(ap[v] + kn);
            #pragma unroll
            for (int v = 0; v < NWV; ++v)
                rw[v] = wv[v] ? *(const float4*)(wp[v] + kn) : make_float4(0.f, 0.f, 0.f, 0.f);
        }
        #pragma unroll
        for (int k = 0; k < 32; ++k) {
            const float4 a0 = *(const float4*)&As[k * 36 + rq * 8];
            const float4 a1 = *(const float4*)&As[k * 36 + rq * 8 + 4];
            float av[8] = {a0.x, a0.y, a0.z, a0.w, a1.x, a1.y, a1.z, a1.w};
            if (NC == 2) {
                const float2 w2 = *(const float2*)&Ws[k * 66 + tx * 2];
                #pragma unroll
                for (int q = 0; q < 8; ++q) {
                    acc[q][0] += av[q] * w2.x;
                    acc[q][1] += av[q] * w2.y;
                }
            } else {
                const float w = Ws[k * 33 + tx];
                #pragma unroll
                for (int q = 0; q < 8; ++q) acc[q][0] += av[q] * w;
            }
        }
        __syncthreads();
    }
}

template<int NC>
__device__ __forceinline__ void acc_zero(float acc[8][NC]) {
    #pragma unroll
    for (int i = 0; i < 8; ++i)
        #pragma unroll
        for (int j = 0; j < NC; ++j) acc[i][j] = 0.f;
}

// kg1 dumps its accumulators into comb[t][*]
__device__ __forceinline__ void dump2(float acc[8][2], float* cb) {
    #pragma unroll
    for (int i = 0; i < 8; ++i) { cb[i * 2] = acc[i][0]; cb[i * 2 + 1] = acc[i][1]; }
}
__device__ __forceinline__ void dump1(float acc[8][1], float* cb) {
    #pragma unroll
    for (int i = 0; i < 8; ++i) cb[i] = acc[i][0];
}

// 256-thread kernels: two K-groups, kg1 dumps acc to comb, kg0 adds + outputs.
#define SMEM_256_NC2 \
    __shared__ float As[2][32*36], Ws[2][32*66]; \
    __shared__ float comb[128][16]; \
    __shared__ unsigned int ro[32];
#define SMEM_256_NC1 \
    __shared__ float As[2][32*36], Ws[2][32*33]; \
    __shared__ float comb[128][8]; \
    __shared__ unsigned int ro[32];

// ---------------------------------------------------------------------------
// setup
// ---------------------------------------------------------------------------
__global__ void k_mean(const float* __restrict__ feat) {
    int idx = blockIdx.x * 256 + threadIdx.x;
    if (blockIdx.x == 0 && threadIdx.x < BB)
        g_best[threadIdx.x] = (unsigned long long)(0xffffffffu - 1u);   // token = SOS = 1
    if (idx >= BB * FF) return;
    int b = idx / FF, f = idx % FF;
    const float* p0 = feat + (size_t)b * PP * FF + f;
    float s = 0.f;
    #pragma unroll 4
    for (int p = 0; p < PP; ++p) s += p0[(size_t)p * FF];
    g_mean[idx] = s * (1.0f / PP);
}

// 256 threads, in-block K-split (two 640 halves of FF).
__global__ void k_inithc(const float* __restrict__ ihw, const float* __restrict__ ihb,
                         const float* __restrict__ icw, const float* __restrict__ icb) {
    SMEM_256_NC2
    float acc[8][2]; acc_zero<2>(acc);
    const int tid = threadIdx.x;
    const int kg = tid >> 7, t = tid & 127;
    int bx = blockIdx.x;
    bool ish = bx < 8;
    int col0 = (ish ? bx : bx - 8) * 64;
    const float* W = ish ? ihw : icw;
    const float* bias = ish ? ihb : icb;
    float* C = ish ? g_h : g_c;
    if (tid < 32) ro[tid] = tid * FF;
    gemm_core<2, 0>(t, g_mean + kg * 640, ro, W + kg * 640, FF, 640, col0, 64, 0,
                    acc, As[kg], Ws[kg]);
    if (kg == 1) dump2(acc, comb[t]);
    __syncthreads();
    if (kg == 0) {
        const int tx = t & 31, rq = t >> 5;
        #pragma unroll
        for (int i = 0; i < 8; ++i)
            #pragma unroll
            for (int j = 0; j < 2; ++j) {
                int c = col0 + tx * 2 + j;
                C[(rq * 8 + i) * HH + c] = acc[i][j] + comb[t][i * 2 + j] + bias[c];
            }
    }
}

__global__ void k_encproj(const float* __restrict__ feat,
                          const float* __restrict__ W2_w, const float* __restrict__ W2_b) {
    SMEM_256_NC2
    float acc[8][2]; acc_zero<2>(acc);
    const int tid = threadIdx.x;
    const int kg = tid >> 7, t = tid & 127;
    int col0 = blockIdx.x * 64;
    int m0 = blockIdx.y * 32;
    if (tid < 32) ro[tid] = tid * FF;
    gemm_core<2, 0>(t, feat + (size_t)m0 * FF + kg * 640, ro, W2_w + kg * 640, FF, 640,
                    col0, 64, 0, acc, As[kg], Ws[kg]);
    if (kg == 1) dump2(acc, comb[t]);
    __syncthreads();
    if (kg == 0) {
        const int tx = t & 31, rq = t >> 5;
        #pragma unroll
        for (int i = 0; i < 8; ++i)
            #pragma unroll
            for (int j = 0; j < 2; ++j) {
                int c = col0 + tx * 2 + j;
                g_encproj[(size_t)(m0 + rq * 8 + i) * HH + c] = acc[i][j] + comb[t][i * 2 + j] + W2_b[c];
            }
    }
}

// ---------------------------------------------------------------------------
// per-step kernels
// ---------------------------------------------------------------------------
// K1: 368 blocks x 256 thr = 4 K-quarters x 92 col-tiles; kg halves each quarter.
__global__ void k_hproj(const float* __restrict__ emb,
                        const float* __restrict__ W1_w, const float* __restrict__ W1_b,
                        const float* __restrict__ gate_w, const float* __restrict__ gate_b,
                        const float* __restrict__ Whh, const float* __restrict__ Wih,
                        const float* __restrict__ bih, const float* __restrict__ bhh) {
    SMEM_256_NC2
    float acc[8][2]; acc_zero<2>(acc);
    const int bx = blockIdx.x;
    const int q = bx & 3, u = bx >> 2;
    const int tid = threadIdx.x;
    const int kg = tid >> 7, t = tid & 127;
    const int koff = q * 128 + kg * 64;
    if (u < 60) { if (tid < 32) ro[tid] = tid * HH; }
    else if (tid < 32) {
        unsigned int tok = 0xffffffffu - (unsigned int)(g_best[tid] & 0xffffffffull);
        ro[tid] = tok * EE;
    }
    const int tx = t & 31, rq = t >> 5;
    if (u < 8) {
        int col0 = u * 64;
        gemm_core<2, 0>(t, g_h + koff, ro, W1_w + koff, HH, 64, col0, 64, 0, acc, As[kg], Ws[kg]);
        if (kg == 1) dump2(acc, comb[t]);
        __syncthreads();
        if (kg == 0) {
            #pragma unroll
            for (int i = 0; i < 8; ++i)
                #pragma unroll
                for (int j = 0; j < 2; ++j) {
                    int c = col0 + tx * 2 + j;
                    g_hid4[q][(rq * 8 + i) * HH + c] = acc[i][j] + comb[t][i * 2 + j] + (q == 0 ? W1_b[c] : 0.f);
                }
        }
    } else if (u < 28) {
        int col0 = (u - 8) * 64;
        gemm_core<2, 0>(t, g_h + koff, ro, gate_w + koff, HH, 64, col0, 64, 0, acc, As[kg], Ws[kg]);
        if (kg == 1) dump2(acc, comb[t]);
        __syncthreads();
        if (kg == 0) {
            #pragma unroll
            for (int i = 0; i < 8; ++i)
                #pragma unroll
                for (int j = 0; j < 2; ++j) {
                    int c = col0 + tx * 2 + j;
                    g_glin4[q][(rq * 8 + i) * FF + c] = acc[i][j] + comb[t][i * 2 + j] + (q == 0 ? gate_b[c] : 0.f);
                }
        }
    } else if (u < 60) {
        int col0 = (u - 28) * 64;
        gemm_core<2, 0>(t, g_h + koff, ro, Whh + koff, HH, 64, col0, 64, 0, acc, As[kg], Ws[kg]);
        if (kg == 1) dump2(acc, comb[t]);
        __syncthreads();
        if (kg == 0) {
            #pragma unroll
            for (int i = 0; i < 8; ++i)
                #pragma unroll
                for (int j = 0; j < 2; ++j) {
                    int c = col0 + tx * 2 + j;
                    g_g04[q][(rq * 8 + i) * G4 + c] = acc[i][j] + comb[t][i * 2 + j] + (q == 0 ? bih[c] + bhh[c] : 0.f);
                }
        }
    } else {
        int col0 = (u - 60) * 64;
        gemm_core<2, 0>(t, emb + koff, ro, Wih + koff, XD, 64, col0, 64, 0, acc, As[kg], Ws[kg]);
        if (kg == 1) dump2(acc, comb[t]);
        __syncthreads();
        if (kg == 0) {
            #pragma unroll
            for (int i = 0; i < 8; ++i)
                #pragma unroll
                for (int j = 0; j < 2; ++j) {
                    int c = col0 + tx * 2 + j;
                    g_g04[4 + q][(rq * 8 + i) * G4 + c] = acc[i][j] + comb[t][i * 2 + j];
                }
        }
    }
}

// K2: scores[b,p] = relu(hid[b]+encproj[b,p]).Va + Va_b ; grid (7, 32), 256 thr
__global__ void k_scores(const float* __restrict__ Va_w, const float* __restrict__ Va_b) {
    const int b = blockIdx.y;
    const int p0 = blockIdx.x * 28;
    const int tid = threadIdx.x;
    __shared__ float4 hv[128], vv[128];
    if (tid < 128) {
        float4 s0 = ((const float4*)(g_hid4[0] + b * HH))[tid];
        float4 s1 = ((const float4*)(g_hid4[1] + b * HH))[tid];
        float4 s2 = ((const float4*)(g_hid4[2] + b * HH))[tid];
        float4 s3 = ((const float4*)(g_hid4[3] + b * HH))[tid];
        hv[tid] = make_float4(s0.x + s1.x + s2.x + s3.x, s0.y + s1.y + s2.y + s3.y,
                              s0.z + s1.z + s2.z + s3.z, s0.w + s1.w + s2.w + s3.w);
        vv[tid] = ((const float4*)Va_w)[tid];
    }
    __syncthreads();
    const int wid = tid >> 5, ln = tid & 31;
    const float vb = Va_b[0];
    for (int p = p0 + wid; p < p0 + 28; p += 8) {
        const float4* ep = (const float4*)(g_encproj + ((size_t)b * PP + p) * HH);
        float s = 0.f;
        #pragma unroll
        for (int u = 0; u < 4; ++u) {
            const float4 e = ep[ln + 32 * u];
            const float4 h = hv[ln + 32 * u];
            const float4 va = vv[ln + 32 * u];
            float t;
            t = h.x + e.x; if (t > 0.f) s += t * va.x;
            t = h.y + e.y; if (t > 0.f) s += t * va.y;
            t = h.z + e.z; if (t > 0.f) s += t * va.z;
            t = h.w + e.w; if (t > 0.f) s += t * va.w;
        }
        #pragma unroll
        for (int off = 16; off; off >>= 1) s += __shfl_xor_sync(0xffffffffu, s, off);
        if (ln == 0) g_sc[b * PP + p] = s + vb;
    }
}

// K3: softmax -> weights; context = w^T @ feat (4-way p-split); * sigmoid(glin)
__global__ void k_ctx(const float* __restrict__ feat, float* __restrict__ attn_t) {
    const int bx = blockIdx.x;                     // 320
    const int b = bx / 10, f0 = (bx % 10) * 128;
    const int tid = threadIdx.x;                   // 512
    __shared__ float ws[PP];
    __shared__ float red[512];
    __shared__ float part[4][128];
    float v = (tid < PP) ? g_sc[b * PP + tid] : -INFINITY;
    red[tid] = v; __syncthreads();
    for (int st = 256; st > 0; st >>= 1) { if (tid < st) red[tid] = fmaxf(red[tid], red[tid + st]); __syncthreads(); }
    const float mx = red[0];
    __syncthreads();
    float e = (tid < PP) ? expf(v - mx) : 0.f;
    red[tid] = e; __syncthreads();
    for (int st = 256; st > 0; st >>= 1) { if (tid < st) red[tid] += red[tid + st]; __syncthreads(); }
    const float inv = 1.0f / red[0];
    if (tid < PP) {
        float w = e * inv;
        ws[tid] = w;
        if (f0 == 0) attn_t[(size_t)b * TT * PP + tid] = w;
    }
    __syncthreads();
    const int fl = tid & 127, pc = tid >> 7;
    const float* fb = feat + (size_t)b * PP * FF + f0 + fl;
    const int ps = pc * 49;
    float acc = 0.f;
    #pragma unroll 7
    for (int p = ps; p < ps + 49; ++p) acc += ws[p] * fb[(size_t)p * FF];
    part[pc][fl] = acc;
    __syncthreads();
    if (tid < 128) {
        const int fi = b * FF + f0 + tid;
        float gl = g_glin4[0][fi] + g_glin4[1][fi] + g_glin4[2][fi] + g_glin4[3][fi];
        float a = part[0][tid] + part[1][tid] + part[2][tid] + part[3][tid];
        g_ctx[b * FF + f0 + tid] = a * sigmoidf(gl);
    }
}

// K4: gtp[q] = ctx[:, q*320..] @ WihF^T slice. 256 blocks x 256 thr; kg splits 320->160.
__global__ void k_gates(const float* __restrict__ Wih) {
    SMEM_256_NC1
    float acc[8][1]; acc_zero<1>(acc);
    const int bx = blockIdx.x;
    const int q = bx & 3, u = bx >> 2;             // u: 0..63, j0 = u*8
    const int tid = threadIdx.x;
    const int kg = tid >> 7, t = tid & 127;
    const int koff = q * 320 + kg * 160;
    const int j0 = u * 8;
    if (tid < 32) ro[tid] = tid * FF;
    gemm_core<1, 1>(t, g_ctx + koff, ro, Wih + EE + koff, XD, 160, 0, 32, j0, acc, As[kg], Ws[kg]);
    if (kg == 1) dump1(acc, comb[t]);
    __syncthreads();
    if (kg == 0) {
        const int tx = t & 31, rq = t >> 5;
        const int g = tx >> 3, jj = tx & 7;
        const int ac = (g << 9) + j0 + jj;
        #pragma unroll
        for (int i = 0; i < 8; ++i) {
            int r = rq * 8 + i;
            g_gtp4[q][r * G4 + ac] = acc[i][0] + comb[t][i];
        }
    }
}

// K4b: sum 12 partials per gate element, LSTM elementwise, reset g_best. 64x256.
__global__ void k_lstm() {
    const int idx = blockIdx.x * 256 + threadIdx.x;    // 0..16383 (b, j)
    if (blockIdx.x == 0 && threadIdx.x < 32) g_best[threadIdx.x] = 0ull;
    const int b = idx >> 9, j = idx & 511;
    float gv[4];
    #pragma unroll
    for (int g = 0; g < 4; ++g) {
        const int c = b * G4 + (g << 9) + j;
        float s = 0.f;
        #pragma unroll
        for (int q = 0; q < 4; ++q)
            s += g_g04[q][c] + g_g04[4 + q][c] + g_gtp4[q][c];
        gv[g] = s;
    }
    float ig = sigmoidf(gv[0]);
    float fg = sigmoidf(gv[1]);
    float gg = tanhf(gv[2]);
    float og = sigmoidf(gv[3]);
    float c = fg * g_c[idx] + ig * gg;
    g_c[idx] = c;
    g_h[idx] = og * tanhf(c);
}

// K5: logits + fused argmax. 313 blocks x 256 thr; kg splits K=512 -> 256.
__global__ void k_logits(const float* __restrict__ out_w, const float* __restrict__ out_b,
                         float* __restrict__ dec_t) {
    SMEM_256_NC1
    float acc[8][1]; acc_zero<1>(acc);
    const int bx = blockIdx.x;
    const int col0 = bx * 32;
    const int nvalid = min(32, VV - col0);
    const int tid = threadIdx.x;
    const int kg = tid >> 7, t = tid & 127;
    if (tid < 32) ro[tid] = tid * HH;
    gemm_core<1, 0>(t, g_h + kg * 256, ro, out_w + kg * 256, HH, 256, col0, nvalid, 0,
                    acc, As[kg], Ws[kg]);
    if (kg == 1) dump1(acc, comb[t]);
    __syncthreads();
    if (kg == 0) {
        const int tx = t & 31, rq = t >> 5;
        const bool val = (tx < nvalid);
        const int c = col0 + tx;
        const float ob = val ? out_b[c] : 0.f;
        #pragma unroll
        for (int i = 0; i < 8; ++i) {
            const int r = rq * 8 + i;
            unsigned long long pk = 0ull;
            if (val) {
                float vv = acc[i][0] + comb[t][i] + ob;
                dec_t[(size_t)r * TT * VV + c] = vv;
                pk = ((unsigned long long)fkey(vv) << 32) | (0xffffffffu - (unsigned int)c);
            }
            #pragma unroll
            for (int off = 16; off; off >>= 1) {
                unsigned long long o = __shfl_xor_sync(0xffffffffu, pk, off);
                if (o > pk) pk = o;
            }
            if (tx == 0) atomicMax(&g_best[r], pk);
        }
    }
}

__global__ void k_copyhc(float* __restrict__ hout, float* __restrict__ cout) {
    int idx = blockIdx.x * 256 + threadIdx.x;
    if (idx < BB * HH) hout[idx] = g_h[idx];
    else if (idx < 2 * BB * HH) cout[idx - BB * HH] = g_c[idx - BB * HH];
}

// ---------------------------------------------------------------------------
extern "C" void kernel_launch(void* const* d_in, const int* in_sizes, int n_in,
                              void* d_out, int out_size) {
    const float* feat   = (const float*)d_in[0];
    const float* emb    = (const float*)d_in[3];
    const float* W1_w   = (const float*)d_in[4];
    const float* W1_b   = (const float*)d_in[5];
    const float* W2_w   = (const float*)d_in[6];
    const float* W2_b   = (const float*)d_in[7];
    const float* Va_w   = (const float*)d_in[8];
    const float* Va_b   = (const float*)d_in[9];
    const float* Wih    = (const float*)d_in[10];
    const float* Whh    = (const float*)d_in[11];
    const float* bih    = (const float*)d_in[12];
    const float* bhh    = (const float*)d_in[13];
    const float* out_w  = (const float*)d_in[14];
    const float* out_b  = (const float*)d_in[15];
    const float* ihw    = (const float*)d_in[16];
    const float* ihb    = (const float*)d_in[17];
    const float* icw    = (const float*)d_in[18];
    const float* icb    = (const float*)d_in[19];
    const float* gate_w = (const float*)d_in[20];
    const float* gate_b = (const float*)d_in[21];

    float* out  = (float*)d_out;
    float* dec  = out;                                   // [B, T, V]
    float* hout = out + (size_t)BB * TT * VV;            // [B, H]
    float* cout = hout + (size_t)BB * HH;                // [B, H]
    float* attn = cout + (size_t)BB * HH;                // [B, T, P]

    k_mean<<<160, 256>>>(feat);
    k_inithc<<<16, 256>>>(ihw, ihb, icw, icb);
    k_encproj<<<dim3(8, 196), 256>>>(feat, W2_w, W2_b);

    for (int t = 0; t < TT; ++t) {
        k_hproj<<<368, 256>>>(emb, W1_w, W1_b, gate_w, gate_b, Whh, Wih, bih, bhh);
        k_scores<<<dim3(7, 32), 256>>>(Va_w, Va_b);
        k_ctx<<<320, 512>>>(feat, attn + (size_t)t * PP);
        k_gates<<<256, 256>>>(Wih);
        k_lstm<<<64, 256>>>();
        k_logits<<<313, 256>>>(out_w, out_b, dec + (size_t)t * VV);
    }
    k_copyhc<<<128, 256>>>(hout, cout);
}

// round 11
// speedup vs baseline: 1.9932x; 1.1208x over previous
#include <cuda_runtime.h>
#include <math.h>
#include <limits.h>

#define BB 32
#define HH 512
#define EE 512
#define VV 10000
#define FF 1280
#define PP 196
#define TT 80
#define G4 2048
#define XD 1792

// ---------------- scratch ---------------------------------------------------
__device__ float g_mean[BB * FF];
__device__ float g_h[BB * HH];
__device__ float g_c[BB * HH];
__device__ float g_hid4[4][BB * HH];     // W1 partials (K quarters)
__device__ float g_glin4[4][BB * FF];    // gate partials
__device__ float g_g04[8][BB * G4];      // [0..3]=Whh quarters, [4..7]=WihE quarters
__device__ float g_gtp4[4][BB * G4];     // ctx@WihF quarters
__device__ float g_sc[BB * PP];
__device__ float g_ctx[BB * FF];
__device__ float g_encproj[BB * PP * HH];
__device__ unsigned long long g_best[BB];

__device__ __forceinline__ float sigmoidf(float x) { return 1.0f / (1.0f + expf(-x)); }

__device__ __forceinline__ unsigned int fkey(float f) {
    unsigned int u = __float_as_uint(f);
    return (u & 0x80000000u) ? ~u : (u | 0x80000000u);
}

// ---------------------------------------------------------------------------
// 128-lane GEMM tile core (one K-group of a 256-thread block).
// 32 rows x (NC*32) cols, K % 32 == 0. t = lane id within the group (0..127).
// As layout [k][row] stride 36; Ws [k][col] stride 66/33.
// MODE 0: W row = col0 + col (col < nvalid). MODE 1: row = (col>>3)*512+j0+(col&7).
// First __syncthreads at TOP (whole block): caller-written ro[] visibility.
// All K-groups in a block must call with the SAME K (matched barriers).
// ---------------------------------------------------------------------------
template<int NC, int MODE>
__device__ __forceinline__ void gemm_core(
    int t,
    const float* __restrict__ A, const unsigned int* __restrict__ rowoff,
    const float* __restrict__ W, int ldw, int K,
    int col0, int nvalid, int j0,
    float acc[8][NC], float* As, float* Ws)
{
    constexpr int NWV = (NC == 2) ? 4 : 2;
    constexpr int WST = (NC == 2) ? 66 : 33;
    const int tx = t & 31, rq = t >> 5;

    __syncthreads();   // ro[] visible; smem buffers free

    const float* ap[2];
    #pragma unroll
    for (int v = 0; v < 2; ++v) {
        int idx = t + v * 128;
        ap[v] = A + rowoff[idx >> 3] + (idx & 7) * 4;
    }
    const float* wp[NWV]; bool wv[NWV];
    #pragma unroll
    for (int v = 0; v < NWV; ++v) {
        int idx = t + v * 128;
        int col = idx >> 3;
        int wr;
        if (MODE == 0) { wr = col0 + col; wv[v] = (col < nvalid); }
        else           { wr = ((col >> 3) << 9) + j0 + (col & 7); wv[v] = true; }
        wp[v] = W + (size_t)wr * ldw + (idx & 7) * 4;
    }

    float4 ra[2], rw[NWV];
    #pragma unroll
    for (int v = 0; v < 2; ++v) ra[v] = *(const float4*)(ap[v]);
    #pragma unroll
    for (int v = 0; v < NWV; ++v)
        rw[v] = wv[v] ? *(const float4*)(wp[v]) : make_float4(0.f, 0.f, 0.f, 0.f);

    for (int k0 = 0; k0 < K; k0 += 32) {
        #pragma unroll
        for (int v = 0; v < 2; ++v) {
            int idx = t + v * 128;
            int row = idx >> 3, kq = idx & 7;
            As[(kq * 4 + 0) * 36 + row] = ra[v].x;
            As[(kq * 4 + 1) * 36 + row] = ra[v].y;
            As[(kq * 4 + 2) * 36 + row] = ra[v].z;
            As[(kq * 4 + 3) * 36 + row] = ra[v].w;
        }
        #pragma unroll
        for (int v = 0; v < NWV; ++v) {
            int idx = t + v * 128;
            int col = idx >> 3, kq = idx & 7;
            Ws[(kq * 4 + 0) * WST + col] = rw[v].x;
            Ws[(kq * 4 + 1) * WST + col] = rw[v].y;
            Ws[(kq * 4 + 2) * WST + col] = rw[v].z;
            Ws[(kq * 4 + 3) * WST + col] = rw[v].w;
        }
        __syncthreads();
        const int kn = k0 + 32;
        if (kn < K) {
            #pragma unroll
            for (int v = 0; v < 2; ++v) ra[v] = *(const float4*)(ap[v] + kn);
            #pragma unroll
            for (int v = 0; v < NWV; ++v)
                rw[v] = wv[v] ? *(const float4*)(wp[v] + kn) : make_float4(0.f, 0.f, 0.f, 0.f);
        }
        #pragma unroll
        for (int k = 0; k < 32; ++k) {
            const float4 a0 = *(const float4*)&As[k * 36 + rq * 8];
            const float4 a1 = *(const float4*)&As[k * 36 + rq * 8 + 4];
            float av[8] = {a0.x, a0.y, a0.z, a0.w, a1.x, a1.y, a1.z, a1.w};
            if (NC == 2) {
                const float2 w2 = *(const float2*)&Ws[k * 66 + tx * 2];
                #pragma unroll
                for (int q = 0; q < 8; ++q) {
                    acc[q][0] += av[q] * w2.x;
                    acc[q][1] += av[q] * w2.y;
                }
            } else {
                const float w = Ws[k * 33 + tx];
                #pragma unroll
                for (int q = 0; q < 8; ++q) acc[q][0] += av[q] * w;
            }
        }
        __syncthreads();
    }
}

template<int NC>
__device__ __forceinline__ void acc_zero(float acc[8][NC]) {
    #pragma unroll
    for (int i = 0; i < 8; ++i)
        #pragma unroll
        for (int j = 0; j < NC; ++j) acc[i][j] = 0.f;
}

__device__ __forceinline__ void dump2(float acc[8][2], float* cb) {
    #pragma unroll
    for (int i = 0; i < 8; ++i) { cb[i * 2] = acc[i][0]; cb[i * 2 + 1] = acc[i][1]; }
}
__device__ __forceinline__ void dump1(float acc[8][1], float* cb) {
    #pragma unroll
    for (int i = 0; i < 8; ++i) cb[i] = acc[i][0];
}

// union smem: big enough for NC2 path; NC1 path uses a prefix of Ws/comb.
#define SMEM_U \
    __shared__ float As[2][32*36], Ws[2][32*66]; \
    __shared__ float comb[128][16]; \
    __shared__ unsigned int ro[32];

// ---------------------------------------------------------------------------
// setup
// ---------------------------------------------------------------------------
__global__ void k_mean(const float* __restrict__ feat) {
    int idx = blockIdx.x * 256 + threadIdx.x;
    if (blockIdx.x == 0 && threadIdx.x < BB)
        g_best[threadIdx.x] = (unsigned long long)(0xffffffffu - 1u);   // token = SOS = 1
    if (idx >= BB * FF) return;
    int b = idx / FF, f = idx % FF;
    const float* p0 = feat + (size_t)b * PP * FF + f;
    float s = 0.f;
    #pragma unroll 4
    for (int p = 0; p < PP; ++p) s += p0[(size_t)p * FF];
    g_mean[idx] = s * (1.0f / PP);
}

__global__ void k_inithc(const float* __restrict__ ihw, const float* __restrict__ ihb,
                         const float* __restrict__ icw, const float* __restrict__ icb) {
    SMEM_U
    float acc[8][2]; acc_zero<2>(acc);
    const int tid = threadIdx.x;
    const int kg = tid >> 7, t = tid & 127;
    int bx = blockIdx.x;
    bool ish = bx < 8;
    int col0 = (ish ? bx : bx - 8) * 64;
    const float* W = ish ? ihw : icw;
    const float* bias = ish ? ihb : icb;
    float* C = ish ? g_h : g_c;
    if (tid < 32) ro[tid] = tid * FF;
    gemm_core<2, 0>(t, g_mean + kg * 640, ro, W + kg * 640, FF, 640, col0, 64, 0,
                    acc, As[kg], Ws[kg]);
    if (kg == 1) dump2(acc, comb[t]);
    __syncthreads();
    if (kg == 0) {
        const int tx = t & 31, rq = t >> 5;
        #pragma unroll
        for (int i = 0; i < 8; ++i)
            #pragma unroll
            for (int j = 0; j < 2; ++j) {
                int c = col0 + tx * 2 + j;
                C[(rq * 8 + i) * HH + c] = acc[i][j] + comb[t][i * 2 + j] + bias[c];
            }
    }
}

__global__ void k_encproj(const float* __restrict__ feat,
                          const float* __restrict__ W2_w, const float* __restrict__ W2_b) {
    SMEM_U
    float acc[8][2]; acc_zero<2>(acc);
    const int tid = threadIdx.x;
    const int kg = tid >> 7, t = tid & 127;
    int col0 = blockIdx.x * 64;
    int m0 = blockIdx.y * 32;
    if (tid < 32) ro[tid] = tid * FF;
    gemm_core<2, 0>(t, feat + (size_t)m0 * FF + kg * 640, ro, W2_w + kg * 640, FF, 640,
                    col0, 64, 0, acc, As[kg], Ws[kg]);
    if (kg == 1) dump2(acc, comb[t]);
    __syncthreads();
    if (kg == 0) {
        const int tx = t & 31, rq = t >> 5;
        #pragma unroll
        for (int i = 0; i < 8; ++i)
            #pragma unroll
            for (int j = 0; j < 2; ++j) {
                int c = col0 + tx * 2 + j;
                g_encproj[(size_t)(m0 + rq * 8 + i) * HH + c] = acc[i][j] + comb[t][i * 2 + j] + W2_b[c];
            }
    }
}

// ---------------------------------------------------------------------------
// FUSED 1: blocks [0, nlog): logits(prev step) -> dec_t + argmax into g_best.
//          blocks [nlog, nlog+240): hprojA (W1 / gate / Whh) for current step.
// Both depend only on g_h (and lstm's g_best reset), so they co-schedule.
// ---------------------------------------------------------------------------
__global__ void k_fused1(int nlog,
                         const float* __restrict__ out_w, const float* __restrict__ out_b,
                         float* __restrict__ dec_t,
                         const float* __restrict__ W1_w, const float* __restrict__ W1_b,
                         const float* __restrict__ gate_w, const float* __restrict__ gate_b,
                         const float* __restrict__ Whh,
                         const float* __restrict__ bih, const float* __restrict__ bhh) {
    SMEM_U
    const int tid = threadIdx.x;
    const int kg = tid >> 7, t = tid & 127;
    if (tid < 32) ro[tid] = tid * HH;            // same for both paths
    const int tx = t & 31, rq = t >> 5;

    if ((int)blockIdx.x < nlog) {
        // ---- logits path: 32 cols per block, kg splits K=512 -> 256 ----
        float acc[8][1]; acc_zero<1>(acc);
        const int bx = blockIdx.x;
        const int col0 = bx * 32;
        const int nvalid = min(32, VV - col0);
        gemm_core<1, 0>(t, g_h + kg * 256, ro, out_w + kg * 256, HH, 256, col0, nvalid, 0,
                        acc, As[kg], Ws[kg]);
        if (kg == 1) dump1(acc, comb[t]);
        __syncthreads();
        if (kg == 0) {
            const bool val = (tx < nvalid);
            const int c = col0 + tx;
            const float ob = val ? out_b[c] : 0.f;
            #pragma unroll
            for (int i = 0; i < 8; ++i) {
                const int r = rq * 8 + i;
                unsigned long long pk = 0ull;
                if (val) {
                    float vv = acc[i][0] + comb[t][i] + ob;
                    dec_t[(size_t)r * TT * VV + c] = vv;
                    pk = ((unsigned long long)fkey(vv) << 32) | (0xffffffffu - (unsigned int)c);
                }
                #pragma unroll
                for (int off = 16; off; off >>= 1) {
                    unsigned long long o = __shfl_xor_sync(0xffffffffu, pk, off);
                    if (o > pk) pk = o;
                }
                if (tx == 0) atomicMax(&g_best[r], pk);
            }
        }
    } else {
        // ---- hprojA path: 240 blocks = 4 K-quarters x 60 col-tiles ----
        float acc[8][2]; acc_zero<2>(acc);
        const int bx = blockIdx.x - nlog;
        const int q = bx & 3, u = bx >> 2;          // u: 0..59
        const int koff = q * 128 + kg * 64;
        if (u < 8) {
            int col0 = u * 64;
            gemm_core<2, 0>(t, g_h + koff, ro, W1_w + koff, HH, 64, col0, 64, 0, acc, As[kg], Ws[kg]);
            if (kg == 1) dump2(acc, comb[t]);
            __syncthreads();
            if (kg == 0) {
                #pragma unroll
                for (int i = 0; i < 8; ++i)
                    #pragma unroll
                    for (int j = 0; j < 2; ++j) {
                        int c = col0 + tx * 2 + j;
                        g_hid4[q][(rq * 8 + i) * HH + c] = acc[i][j] + comb[t][i * 2 + j] + (q == 0 ? W1_b[c] : 0.f);
                    }
            }
        } else if (u < 28) {
            int col0 = (u - 8) * 64;
            gemm_core<2, 0>(t, g_h + koff, ro, gate_w + koff, HH, 64, col0, 64, 0, acc, As[kg], Ws[kg]);
            if (kg == 1) dump2(acc, comb[t]);
            __syncthreads();
            if (kg == 0) {
                #pragma unroll
                for (int i = 0; i < 8; ++i)
                    #pragma unroll
                    for (int j = 0; j < 2; ++j) {
                        int c = col0 + tx * 2 + j;
                        g_glin4[q][(rq * 8 + i) * FF + c] = acc[i][j] + comb[t][i * 2 + j] + (q == 0 ? gate_b[c] : 0.f);
                    }
            }
        } else {
            int col0 = (u - 28) * 64;
            gemm_core<2, 0>(t, g_h + koff, ro, Whh + koff, HH, 64, col0, 64, 0, acc, As[kg], Ws[kg]);
            if (kg == 1) dump2(acc, comb[t]);
            __syncthreads();
            if (kg == 0) {
                #pragma unroll
                for (int i = 0; i < 8; ++i)
                    #pragma unroll
                    for (int j = 0; j < 2; ++j) {
                        int c = col0 + tx * 2 + j;
                        g_g04[q][(rq * 8 + i) * G4 + c] = acc[i][j] + comb[t][i * 2 + j] + (q == 0 ? bih[c] + bhh[c] : 0.f);
                    }
            }
        }
    }
}

// ---------------------------------------------------------------------------
// FUSED 2: blocks [0, 224): scores (p-tile px=bx%7, batch b=bx/7).
//          blocks [224, 352): hprojB = emb[g_best token] @ WihE^T.
// scores needs g_hid4 (fused1); hprojB needs g_best (logits in fused1). Disjoint.
// ---------------------------------------------------------------------------
__global__ void k_fused2(const float* __restrict__ Va_w, const float* __restrict__ Va_b,
                         const float* __restrict__ emb, const float* __restrict__ Wih) {
    SMEM_U
    const int tid = threadIdx.x;
    if ((int)blockIdx.x < 224) {
        // ---- scores path ----
        __shared__ float4 hv[128], vv[128];
        const int b = blockIdx.x / 7;
        const int p0 = (blockIdx.x % 7) * 28;
        if (tid < 128) {
            float4 s0 = ((const float4*)(g_hid4[0] + b * HH))[tid];
            float4 s1 = ((const float4*)(g_hid4[1] + b * HH))[tid];
            float4 s2 = ((const float4*)(g_hid4[2] + b * HH))[tid];
            float4 s3 = ((const float4*)(g_hid4[3] + b * HH))[tid];
            hv[tid] = make_float4(s0.x + s1.x + s2.x + s3.x, s0.y + s1.y + s2.y + s3.y,
                                  s0.z + s1.z + s2.z + s3.z, s0.w + s1.w + s2.w + s3.w);
            vv[tid] = ((const float4*)Va_w)[tid];
        }
        __syncthreads();
        const int wid = tid >> 5, ln = tid & 31;
        const float vb = Va_b[0];
        for (int p = p0 + wid; p < p0 + 28; p += 8) {
            const float4* ep = (const float4*)(g_encproj + ((size_t)b * PP + p) * HH);
            float s = 0.f;
            #pragma unroll
            for (int u = 0; u < 4; ++u) {
                const float4 e = ep[ln + 32 * u];
                const float4 h = hv[ln + 32 * u];
                const float4 va = vv[ln + 32 * u];
                float t0;
                t0 = h.x + e.x; if (t0 > 0.f) s += t0 * va.x;
                t0 = h.y + e.y; if (t0 > 0.f) s += t0 * va.y;
                t0 = h.z + e.z; if (t0 > 0.f) s += t0 * va.z;
                t0 = h.w + e.w; if (t0 > 0.f) s += t0 * va.w;
            }
            #pragma unroll
            for (int off = 16; off; off >>= 1) s += __shfl_xor_sync(0xffffffffu, s, off);
            if (ln == 0) g_sc[b * PP + p] = s + vb;
        }
    } else {
        // ---- hprojB path: 128 blocks = 4 K-quarters x 32 col-tiles ----
        float acc[8][2]; acc_zero<2>(acc);
        const int bx = blockIdx.x - 224;
        const int q = bx & 3, u = bx >> 2;          // u: 0..31
        const int kg = tid >> 7, t = tid & 127;
        const int koff = q * 128 + kg * 64;
        if (tid < 32) {
            unsigned int tok = 0xffffffffu - (unsigned int)(g_best[tid] & 0xffffffffull);
            ro[tid] = tok * EE;
        }
        const int tx = t & 31, rq = t >> 5;
        const int col0 = u * 64;
        gemm_core<2, 0>(t, emb + koff, ro, Wih + koff, XD, 64, col0, 64, 0, acc, As[kg], Ws[kg]);
        if (kg == 1) dump2(acc, comb[t]);
        __syncthreads();
        if (kg == 0) {
            #pragma unroll
            for (int i = 0; i < 8; ++i)
                #pragma unroll
                for (int j = 0; j < 2; ++j) {
                    int c = col0 + tx * 2 + j;
                    g_g04[4 + q][(rq * 8 + i) * G4 + c] = acc[i][j] + comb[t][i * 2 + j];
                }
        }
    }
}

// K3: softmax -> weights; context = w^T @ feat (4-way p-split); * sigmoid(glin)
__global__ void k_ctx(const float* __restrict__ feat, float* __restrict__ attn_t) {
    const int bx = blockIdx.x;                     // 320
    const int b = bx / 10, f0 = (bx % 10) * 128;
    const int tid = threadIdx.x;                   // 512
    __shared__ float ws[PP];
    __shared__ float red[512];
    __shared__ float part[4][128];
    float v = (tid < PP) ? g_sc[b * PP + tid] : -INFINITY;
    red[tid] = v; __syncthreads();
    for (int st = 256; st > 0; st >>= 1) { if (tid < st) red[tid] = fmaxf(red[tid], red[tid + st]); __syncthreads(); }
    const float mx = red[0];
    __syncthreads();
    float e = (tid < PP) ? expf(v - mx) : 0.f;
    red[tid] = e; __syncthreads();
    for (int st = 256; st > 0; st >>= 1) { if (tid < st) red[tid] += red[tid + st]; __syncthreads(); }
    const float inv = 1.0f / red[0];
    if (tid < PP) {
        float w = e * inv;
        ws[tid] = w;
        if (f0 == 0) attn_t[(size_t)b * TT * PP + tid] = w;
    }
    __syncthreads();
    const int fl = tid & 127, pc = tid >> 7;
    const float* fb = feat + (size_t)b * PP * FF + f0 + fl;
    const int ps = pc * 49;
    float acc = 0.f;
    #pragma unroll 7
    for (int p = ps; p < ps + 49; ++p) acc += ws[p] * fb[(size_t)p * FF];
    part[pc][fl] = acc;
    __syncthreads();
    if (tid < 128) {
        const int fi = b * FF + f0 + tid;
        float gl = g_glin4[0][fi] + g_glin4[1][fi] + g_glin4[2][fi] + g_glin4[3][fi];
        float a = part[0][tid] + part[1][tid] + part[2][tid] + part[3][tid];
        g_ctx[b * FF + f0 + tid] = a * sigmoidf(gl);
    }
}

// K4: gtp[q] = ctx[:, q*320..] @ WihF^T slice. 256 blocks x 256 thr; kg splits 320->160.
__global__ void k_gates(const float* __restrict__ Wih) {
    SMEM_U
    float acc[8][1]; acc_zero<1>(acc);
    const int bx = blockIdx.x;
    const int q = bx & 3, u = bx >> 2;             // u: 0..63, j0 = u*8
    const int tid = threadIdx.x;
    const int kg = tid >> 7, t = tid & 127;
    const int koff = q * 320 + kg * 160;
    const int j0 = u * 8;
    if (tid < 32) ro[tid] = tid * FF;
    gemm_core<1, 1>(t, g_ctx + koff, ro, Wih + EE + koff, XD, 160, 0, 32, j0, acc, As[kg], Ws[kg]);
    if (kg == 1) dump1(acc, comb[t]);
    __syncthreads();
    if (kg == 0) {
        const int tx = t & 31, rq = t >> 5;
        const int g = tx >> 3, jj = tx & 7;
        const int ac = (g << 9) + j0 + jj;
        #pragma unroll
        for (int i = 0; i < 8; ++i) {
            int r = rq * 8 + i;
            g_gtp4[q][r * G4 + ac] = acc[i][0] + comb[t][i];
        }
    }
}

// K4b: sum 12 partials per gate element, LSTM elementwise, reset g_best. 64x256.
__global__ void k_lstm() {
    const int idx = blockIdx.x * 256 + threadIdx.x;    // 0..16383 (b, j)
    if (blockIdx.x == 0 && threadIdx.x < 32) g_best[threadIdx.x] = 0ull;
    const int b = idx >> 9, j = idx & 511;
    float gv[4];
    #pragma unroll
    for (int g = 0; g < 4; ++g) {
        const int c = b * G4 + (g << 9) + j;
        float s = 0.f;
        #pragma unroll
        for (int q = 0; q < 4; ++q)
            s += g_g04[q][c] + g_g04[4 + q][c] + g_gtp4[q][c];
        gv[g] = s;
    }
    float ig = sigmoidf(gv[0]);
    float fg = sigmoidf(gv[1]);
    float gg = tanhf(gv[2]);
    float og = sigmoidf(gv[3]);
    float c = fg * g_c[idx] + ig * gg;
    g_c[idx] = c;
    g_h[idx] = og * tanhf(c);
}

__global__ void k_copyhc(float* __restrict__ hout, float* __restrict__ cout) {
    int idx = blockIdx.x * 256 + threadIdx.x;
    if (idx < BB * HH) hout[idx] = g_h[idx];
    else if (idx < 2 * BB * HH) cout[idx - BB * HH] = g_c[idx - BB * HH];
}

// ---------------------------------------------------------------------------
extern "C" void kernel_launch(void* const* d_in, const int* in_sizes, int n_in,
                              void* d_out, int out_size) {
    const float* feat   = (const float*)d_in[0];
    const float* emb    = (const float*)d_in[3];
    const float* W1_w   = (const float*)d_in[4];
    const float* W1_b   = (const float*)d_in[5];
    const float* W2_w   = (const float*)d_in[6];
    const float* W2_b   = (const float*)d_in[7];
    const float* Va_w   = (const float*)d_in[8];
    const float* Va_b   = (const float*)d_in[9];
    const float* Wih    = (const float*)d_in[10];
    const float* Whh    = (const float*)d_in[11];
    const float* bih    = (const float*)d_in[12];
    const float* bhh    = (const float*)d_in[13];
    const float* out_w  = (const float*)d_in[14];
    const float* out_b  = (const float*)d_in[15];
    const float* ihw    = (const float*)d_in[16];
    const float* ihb    = (const float*)d_in[17];
    const float* icw    = (const float*)d_in[18];
    const float* icb    = (const float*)d_in[19];
    const float* gate_w = (const float*)d_in[20];
    const float* gate_b = (const float*)d_in[21];

    float* out  = (float*)d_out;
    float* dec  = out;                                   // [B, T, V]
    float* hout = out + (size_t)BB * TT * VV;            // [B, H]
    float* cout = hout + (size_t)BB * HH;                // [B, H]
    float* attn = cout + (size_t)BB * HH;                // [B, T, P]

    k_mean<<<160, 256>>>(feat);
    k_inithc<<<16, 256>>>(ihw, ihb, icw, icb);
    k_encproj<<<dim3(8, 196), 256>>>(feat, W2_w, W2_b);

    for (int t = 0; t < TT; ++t) {
        const int nlog = (t == 0) ? 0 : 313;
        float* dec_prev = dec + (size_t)(t > 0 ? t - 1 : 0) * VV;
        k_fused1<<<nlog + 240, 256>>>(nlog, out_w, out_b, dec_prev,
                                      W1_w, W1_b, gate_w, gate_b, Whh, bih, bhh);
        k_fused2<<<352, 256>>>(Va_w, Va_b, emb, Wih);
        k_ctx<<<320, 512>>>(feat, attn + (size_t)t * PP);
        k_gates<<<256, 256>>>(Wih);
        k_lstm<<<64, 256>>>();
    }
    // tail: logits for the last step (no hprojA)
    k_fused1<<<313, 256>>>(313, out_w, out_b, dec + (size_t)(TT - 1) * VV,
                           W1_w, W1_b, gate_w, gate_b, Whh, bih, bhh);
    k_copyhc<<<128, 256>>>(hout, cout);
}

// round 12
// speedup vs baseline: 2.1304x; 1.0688x over previous
#include <cuda_runtime.h>
#include <math.h>
#include <limits.h>

#define BB 32
#define HH 512
#define EE 512
#define VV 10000
#define FF 1280
#define PP 196
#define TT 80
#define G4 2048
#define XD 1792
#define NLOG 157   // logits col-tiles (64 wide)

// ---------------- scratch ---------------------------------------------------
__device__ float g_mean[BB * FF];
__device__ float g_h[BB * HH];
__device__ float g_c[BB * HH];
__device__ float g_hid4[4][BB * HH];     // W1 partials (K quarters)
__device__ float g_glin4[4][BB * FF];    // gate partials
__device__ float g_g04[8][BB * G4];      // [0..3]=Whh quarters, [4..7]=WihE quarters
__device__ float g_gtp4[4][BB * G4];     // ctx@WihF quarters
__device__ float g_sc[BB * PP];
__device__ float g_ctx[BB * FF];
__device__ float g_encproj[BB * PP * HH];
__device__ unsigned long long g_best[BB];

__device__ __forceinline__ float sigmoidf(float x) { return 1.0f / (1.0f + expf(-x)); }

__device__ __forceinline__ unsigned int fkey(float f) {
    unsigned int u = __float_as_uint(f);
    return (u & 0x80000000u) ? ~u : (u | 0x80000000u);
}

// ---------------------------------------------------------------------------
// 128-lane GEMM tile core (one K-group of a 256-thread block).
// 32 rows x (NC*32) cols, K % 32 == 0. t = lane id within the group (0..127).
// As layout [k][row] stride 36; Ws [k][col] stride 66/33.
// MODE 0: W row = col0 + col (col < nvalid). MODE 1: row = (col>>3)*512+j0+(col&7).
// First __syncthreads at TOP (whole block): caller-written ro[] visibility.
// All K-groups in a block must call with the SAME K (matched barriers).
// ---------------------------------------------------------------------------
template<int NC, int MODE>
__device__ __forceinline__ void gemm_core(
    int t,
    const float* __restrict__ A, const unsigned int* __restrict__ rowoff,
    const float* __restrict__ W, int ldw, int K,
    int col0, int nvalid, int j0,
    float acc[8][NC], float* As, float* Ws)
{
    constexpr int NWV = (NC == 2) ? 4 : 2;
    constexpr int WST = (NC == 2) ? 66 : 33;
    const int tx = t & 31, rq = t >> 5;

    __syncthreads();   // ro[] visible; smem buffers free

    const float* ap[2];
    #pragma unroll
    for (int v = 0; v < 2; ++v) {
        int idx = t + v * 128;
        ap[v] = A + rowoff[idx >> 3] + (idx & 7) * 4;
    }
    const float* wp[NWV]; bool wv[NWV];
    #pragma unroll
    for (int v = 0; v < NWV; ++v) {
        int idx = t + v * 128;
        int col = idx >> 3;
        int wr;
        if (MODE == 0) { wr = col0 + col; wv[v] = (col < nvalid); }
        else           { wr = ((col >> 3) << 9) + j0 + (col & 7); wv[v] = true; }
        wp[v] = W + (size_t)wr * ldw + (idx & 7) * 4;
    }

    float4 ra[2], rw[NWV];
    #pragma unroll
    for (int v = 0; v < 2; ++v) ra[v] = *(const float4*)(ap[v]);
    #pragma unroll
    for (int v = 0; v < NWV; ++v)
        rw[v] = wv[v] ? *(const float4*)(wp[v]) : make_float4(0.f, 0.f, 0.f, 0.f);

    for (int k0 = 0; k0 < K; k0 += 32) {
        #pragma unroll
        for (int v = 0; v < 2; ++v) {
            int idx = t + v * 128;
            int row = idx >> 3, kq = idx & 7;
            As[(kq * 4 + 0) * 36 + row] = ra[v].x;
            As[(kq * 4 + 1) * 36 + row] = ra[v].y;
            As[(kq * 4 + 2) * 36 + row] = ra[v].z;
            As[(kq * 4 + 3) * 36 + row] = ra[v].w;
        }
        #pragma unroll
        for (int v = 0; v < NWV; ++v) {
            int idx = t + v * 128;
            int col = idx >> 3, kq = idx & 7;
            Ws[(kq * 4 + 0) * WST + col] = rw[v].x;
            Ws[(kq * 4 + 1) * WST + col] = rw[v].y;
            Ws[(kq * 4 + 2) * WST + col] = rw[v].z;
            Ws[(kq * 4 + 3) * WST + col] = rw[v].w;
        }
        __syncthreads();
        const int kn = k0 + 32;
        if (kn < K) {
            #pragma unroll
            for (int v = 0; v < 2; ++v) ra[v] = *(const float4*)(ap[v] + kn);
            #pragma unroll
            for (int v = 0; v < NWV; ++v)
                rw[v] = wv[v] ? *(const float4*)(wp[v] + kn) : make_float4(0.f, 0.f, 0.f, 0.f);
        }
        #pragma unroll
        for (int k = 0; k < 32; ++k) {
            const float4 a0 = *(const float4*)&As[k * 36 + rq * 8];
            const float4 a1 = *(const float4*)&As[k * 36 + rq * 8 + 4];
            float av[8] = {a0.x, a0.y, a0.z, a0.w, a1.x, a1.y, a1.z, a1.w};
            if (NC == 2) {
                const float2 w2 = *(const float2*)&Ws[k * 66 + tx * 2];
                #pragma unroll
                for (int q = 0; q < 8; ++q) {
                    acc[q][0] += av[q] * w2.x;
                    acc[q][1] += av[q] * w2.y;
                }
            } else {
                const float w = Ws[k * 33 + tx];
                #pragma unroll
                for (int q = 0; q < 8; ++q) acc[q][0] += av[q] * w;
            }
        }
        __syncthreads();
    }
}

template<int NC>
__device__ __forceinline__ void acc_zero(float acc[8][NC]) {
    #pragma unroll
    for (int i = 0; i < 8; ++i)
        #pragma unroll
        for (int j = 0; j < NC; ++j) acc[i][j] = 0.f;
}

__device__ __forceinline__ void dump2(float acc[8][2], float* cb) {
    #pragma unroll
    for (int i = 0; i < 8; ++i) { cb[i * 2] = acc[i][0]; cb[i * 2 + 1] = acc[i][1]; }
}
__device__ __forceinline__ void dump1(float acc[8][1], float* cb) {
    #pragma unroll
    for (int i = 0; i < 8; ++i) cb[i] = acc[i][0];
}

// union smem: big enough for NC2 path; NC1 path uses a prefix of Ws/comb.
#define SMEM_U \
    __shared__ float As[2][32*36], Ws[2][32*66]; \
    __shared__ float comb[128][16]; \
    __shared__ unsigned int ro[32];

// ---------------------------------------------------------------------------
// setup
// ---------------------------------------------------------------------------
__global__ void k_mean(const float* __restrict__ feat) {
    int idx = blockIdx.x * 256 + threadIdx.x;
    if (blockIdx.x == 0 && threadIdx.x < BB)
        g_best[threadIdx.x] = (unsigned long long)(0xffffffffu - 1u);   // token = SOS = 1
    if (idx >= BB * FF) return;
    int b = idx / FF, f = idx % FF;
    const float* p0 = feat + (size_t)b * PP * FF + f;
    float s = 0.f;
    #pragma unroll 4
    for (int p = 0; p < PP; ++p) s += p0[(size_t)p * FF];
    g_mean[idx] = s * (1.0f / PP);
}

__global__ void k_inithc(const float* __restrict__ ihw, const float* __restrict__ ihb,
                         const float* __restrict__ icw, const float* __restrict__ icb) {
    SMEM_U
    float acc[8][2]; acc_zero<2>(acc);
    const int tid = threadIdx.x;
    const int kg = tid >> 7, t = tid & 127;
    int bx = blockIdx.x;
    bool ish = bx < 8;
    int col0 = (ish ? bx : bx - 8) * 64;
    const float* W = ish ? ihw : icw;
    const float* bias = ish ? ihb : icb;
    float* C = ish ? g_h : g_c;
    if (tid < 32) ro[tid] = tid * FF;
    gemm_core<2, 0>(t, g_mean + kg * 640, ro, W + kg * 640, FF, 640, col0, 64, 0,
                    acc, As[kg], Ws[kg]);
    if (kg == 1) dump2(acc, comb[t]);
    __syncthreads();
    if (kg == 0) {
        const int tx = t & 31, rq = t >> 5;
        #pragma unroll
        for (int i = 0; i < 8; ++i)
            #pragma unroll
            for (int j = 0; j < 2; ++j) {
                int c = col0 + tx * 2 + j;
                C[(rq * 8 + i) * HH + c] = acc[i][j] + comb[t][i * 2 + j] + bias[c];
            }
    }
}

__global__ void k_encproj(const float* __restrict__ feat,
                          const float* __restrict__ W2_w, const float* __restrict__ W2_b) {
    SMEM_U
    float acc[8][2]; acc_zero<2>(acc);
    const int tid = threadIdx.x;
    const int kg = tid >> 7, t = tid & 127;
    int col0 = blockIdx.x * 64;
    int m0 = blockIdx.y * 32;
    if (tid < 32) ro[tid] = tid * FF;
    gemm_core<2, 0>(t, feat + (size_t)m0 * FF + kg * 640, ro, W2_w + kg * 640, FF, 640,
                    col0, 64, 0, acc, As[kg], Ws[kg]);
    if (kg == 1) dump2(acc, comb[t]);
    __syncthreads();
    if (kg == 0) {
        const int tx = t & 31, rq = t >> 5;
        #pragma unroll
        for (int i = 0; i < 8; ++i)
            #pragma unroll
            for (int j = 0; j < 2; ++j) {
                int c = col0 + tx * 2 + j;
                g_encproj[(size_t)(m0 + rq * 8 + i) * HH + c] = acc[i][j] + comb[t][i * 2 + j] + W2_b[c];
            }
    }
}

// ---------------------------------------------------------------------------
// FUSED 1: blocks [0, nlog): logits(prev step), 64 cols/block (NC2), streaming
//          stores to dec + argmax into g_best.
//          blocks [nlog, nlog+240): hprojA (W1 / gate / Whh) for current step.
// ---------------------------------------------------------------------------
__global__ void k_fused1(int nlog,
                         const float* __restrict__ out_w, const float* __restrict__ out_b,
                         float* __restrict__ dec_t,
                         const float* __restrict__ W1_w, const float* __restrict__ W1_b,
                         const float* __restrict__ gate_w, const float* __restrict__ gate_b,
                         const float* __restrict__ Whh,
                         const float* __restrict__ bih, const float* __restrict__ bhh) {
    SMEM_U
    const int tid = threadIdx.x;
    const int kg = tid >> 7, t = tid & 127;
    if (tid < 32) ro[tid] = tid * HH;            // same for both paths
    const int tx = t & 31, rq = t >> 5;

    if ((int)blockIdx.x < nlog) {
        // ---- logits path: 64 cols per block (NC2), kg splits K=512 -> 256 ----
        float acc[8][2]; acc_zero<2>(acc);
        const int bx = blockIdx.x;
        const int col0 = bx * 64;
        const int nvalid = min(64, VV - col0);
        gemm_core<2, 0>(t, g_h + kg * 256, ro, out_w + kg * 256, HH, 256, col0, nvalid, 0,
                        acc, As[kg], Ws[kg]);
        if (kg == 1) dump2(acc, comb[t]);
        __syncthreads();
        if (kg == 0) {
            #pragma unroll
            for (int i = 0; i < 8; ++i) {
                const int r = rq * 8 + i;
                unsigned long long pk = 0ull;
                #pragma unroll
                for (int j = 0; j < 2; ++j) {
                    const int cl = tx * 2 + j;
                    if (cl < nvalid) {
                        const int c = col0 + cl;
                        float vv = acc[i][j] + comb[t][i * 2 + j] + out_b[c];
                        __stcs(&dec_t[(size_t)r * TT * VV + c], vv);   // streaming store
                        unsigned long long p = ((unsigned long long)fkey(vv) << 32)
                                             | (0xffffffffu - (unsigned int)c);
                        if (p > pk) pk = p;
                    }
                }
                #pragma unroll
                for (int off = 16; off; off >>= 1) {
                    unsigned long long o = __shfl_xor_sync(0xffffffffu, pk, off);
                    if (o > pk) pk = o;
                }
                if (tx == 0) atomicMax(&g_best[r], pk);
            }
        }
    } else {
        // ---- hprojA path: 240 blocks = 4 K-quarters x 60 col-tiles ----
        float acc[8][2]; acc_zero<2>(acc);
        const int bx = blockIdx.x - nlog;
        const int q = bx & 3, u = bx >> 2;          // u: 0..59
        const int koff = q * 128 + kg * 64;
        if (u < 8) {
            int col0 = u * 64;
            gemm_core<2, 0>(t, g_h + koff, ro, W1_w + koff, HH, 64, col0, 64, 0, acc, As[kg], Ws[kg]);
            if (kg == 1) dump2(acc, comb[t]);
            __syncthreads();
            if (kg == 0) {
                #pragma unroll
                for (int i = 0; i < 8; ++i)
                    #pragma unroll
                    for (int j = 0; j < 2; ++j) {
                        int c = col0 + tx * 2 + j;
                        g_hid4[q][(rq * 8 + i) * HH + c] = acc[i][j] + comb[t][i * 2 + j] + (q == 0 ? W1_b[c] : 0.f);
                    }
            }
        } else if (u < 28) {
            int col0 = (u - 8) * 64;
            gemm_core<2, 0>(t, g_h + koff, ro, gate_w + koff, HH, 64, col0, 64, 0, acc, As[kg], Ws[kg]);
            if (kg == 1) dump2(acc, comb[t]);
            __syncthreads();
            if (kg == 0) {
                #pragma unroll
                for (int i = 0; i < 8; ++i)
                    #pragma unroll
                    for (int j = 0; j < 2; ++j) {
                        int c = col0 + tx * 2 + j;
                        g_glin4[q][(rq * 8 + i) * FF + c] = acc[i][j] + comb[t][i * 2 + j] + (q == 0 ? gate_b[c] : 0.f);
                    }
            }
        } else {
            int col0 = (u - 28) * 64;
            gemm_core<2, 0>(t, g_h + koff, ro, Whh + koff, HH, 64, col0, 64, 0, acc, As[kg], Ws[kg]);
            if (kg == 1) dump2(acc, comb[t]);
            __syncthreads();
            if (kg == 0) {
                #pragma unroll
                for (int i = 0; i < 8; ++i)
                    #pragma unroll
                    for (int j = 0; j < 2; ++j) {
                        int c = col0 + tx * 2 + j;
                        g_g04[q][(rq * 8 + i) * G4 + c] = acc[i][j] + comb[t][i * 2 + j] + (q == 0 ? bih[c] + bhh[c] : 0.f);
                    }
            }
        }
    }
}

// ---------------------------------------------------------------------------
// FUSED 2: blocks [0, 224): scores. blocks [224, 352): hprojB (emb @ WihE^T).
// ---------------------------------------------------------------------------
__global__ void k_fused2(const float* __restrict__ Va_w, const float* __restrict__ Va_b,
                         const float* __restrict__ emb, const float* __restrict__ Wih) {
    SMEM_U
    const int tid = threadIdx.x;
    if ((int)blockIdx.x < 224) {
        // ---- scores path ----
        __shared__ float4 hv[128], vv[128];
        const int b = blockIdx.x / 7;
        const int p0 = (blockIdx.x % 7) * 28;
        if (tid < 128) {
            float4 s0 = ((const float4*)(g_hid4[0] + b * HH))[tid];
            float4 s1 = ((const float4*)(g_hid4[1] + b * HH))[tid];
            float4 s2 = ((const float4*)(g_hid4[2] + b * HH))[tid];
            float4 s3 = ((const float4*)(g_hid4[3] + b * HH))[tid];
            hv[tid] = make_float4(s0.x + s1.x + s2.x + s3.x, s0.y + s1.y + s2.y + s3.y,
                                  s0.z + s1.z + s2.z + s3.z, s0.w + s1.w + s2.w + s3.w);
            vv[tid] = ((const float4*)Va_w)[tid];
        }
        __syncthreads();
        const int wid = tid >> 5, ln = tid & 31;
        const float vb = Va_b[0];
        for (int p = p0 + wid; p < p0 + 28; p += 8) {
            const float4* ep = (const float4*)(g_encproj + ((size_t)b * PP + p) * HH);
            float s = 0.f;
            #pragma unroll
            for (int u = 0; u < 4; ++u) {
                const float4 e = ep[ln + 32 * u];
                const float4 h = hv[ln + 32 * u];
                const float4 va = vv[ln + 32 * u];
                float t0;
                t0 = h.x + e.x; if (t0 > 0.f) s += t0 * va.x;
                t0 = h.y + e.y; if (t0 > 0.f) s += t0 * va.y;
                t0 = h.z + e.z; if (t0 > 0.f) s += t0 * va.z;
                t0 = h.w + e.w; if (t0 > 0.f) s += t0 * va.w;
            }
            #pragma unroll
            for (int off = 16; off; off >>= 1) s += __shfl_xor_sync(0xffffffffu, s, off);
            if (ln == 0) g_sc[b * PP + p] = s + vb;
        }
    } else {
        // ---- hprojB path: 128 blocks = 4 K-quarters x 32 col-tiles ----
        float acc[8][2]; acc_zero<2>(acc);
        const int bx = blockIdx.x - 224;
        const int q = bx & 3, u = bx >> 2;          // u: 0..31
        const int kg = tid >> 7, t = tid & 127;
        const int koff = q * 128 + kg * 64;
        if (tid < 32) {
            unsigned int tok = 0xffffffffu - (unsigned int)(g_best[tid] & 0xffffffffull);
            ro[tid] = tok * EE;
        }
        const int tx = t & 31, rq = t >> 5;
        const int col0 = u * 64;
        gemm_core<2, 0>(t, emb + koff, ro, Wih + koff, XD, 64, col0, 64, 0, acc, As[kg], Ws[kg]);
        if (kg == 1) dump2(acc, comb[t]);
        __syncthreads();
        if (kg == 0) {
            #pragma unroll
            for (int i = 0; i < 8; ++i)
                #pragma unroll
                for (int j = 0; j < 2; ++j) {
                    int c = col0 + tx * 2 + j;
                    g_g04[4 + q][(rq * 8 + i) * G4 + c] = acc[i][j] + comb[t][i * 2 + j];
                }
        }
    }
}

// K3: softmax -> weights; context = w^T @ feat (4-way p-split); * sigmoid(glin)
__global__ void k_ctx(const float* __restrict__ feat, float* __restrict__ attn_t) {
    const int bx = blockIdx.x;                     // 320
    const int b = bx / 10, f0 = (bx % 10) * 128;
    const int tid = threadIdx.x;                   // 512
    __shared__ float ws[PP];
    __shared__ float red[512];
    __shared__ float part[4][128];
    float v = (tid < PP) ? g_sc[b * PP + tid] : -INFINITY;
    red[tid] = v; __syncthreads();
    for (int st = 256; st > 0; st >>= 1) { if (tid < st) red[tid] = fmaxf(red[tid], red[tid + st]); __syncthreads(); }
    const float mx = red[0];
    __syncthreads();
    float e = (tid < PP) ? expf(v - mx) : 0.f;
    red[tid] = e; __syncthreads();
    for (int st = 256; st > 0; st >>= 1) { if (tid < st) red[tid] += red[tid + st]; __syncthreads(); }
    const float inv = 1.0f / red[0];
    if (tid < PP) {
        float w = e * inv;
        ws[tid] = w;
        if (f0 == 0) __stcs(&attn_t[(size_t)b * TT * PP + tid], w);   // streaming store
    }
    __syncthreads();
    const int fl = tid & 127, pc = tid >> 7;
    const float* fb = feat + (size_t)b * PP * FF + f0 + fl;
    const int ps = pc * 49;
    float acc = 0.f;
    #pragma unroll 7
    for (int p = ps; p < ps + 49; ++p) acc += ws[p] * fb[(size_t)p * FF];
    part[pc][fl] = acc;
    __syncthreads();
    if (tid < 128) {
        const int fi = b * FF + f0 + tid;
        float gl = g_glin4[0][fi] + g_glin4[1][fi] + g_glin4[2][fi] + g_glin4[3][fi];
        float a = part[0][tid] + part[1][tid] + part[2][tid] + part[3][tid];
        g_ctx[b * FF + f0 + tid] = a * sigmoidf(gl);
    }
}

// K4: gtp[q] = ctx[:, q*320..] @ WihF^T slice. 256 blocks x 256 thr; kg splits 320->160.
__global__ void k_gates(const float* __restrict__ Wih) {
    SMEM_U
    float acc[8][1]; acc_zero<1>(acc);
    const int bx = blockIdx.x;
    const int q = bx & 3, u = bx >> 2;             // u: 0..63, j0 = u*8
    const int tid = threadIdx.x;
    const int kg = tid >> 7, t = tid & 127;
    const int koff = q * 320 + kg * 160;
    const int j0 = u * 8;
    if (tid < 32) ro[tid] = tid * FF;
    gemm_core<1, 1>(t, g_ctx + koff, ro, Wih + EE + koff, XD, 160, 0, 32, j0, acc, As[kg], Ws[kg]);
    if (kg == 1) dump1(acc, comb[t]);
    __syncthreads();
    if (kg == 0) {
        const int tx = t & 31, rq = t >> 5;
        const int g = tx >> 3, jj = tx & 7;
        const int ac = (g << 9) + j0 + jj;
        #pragma unroll
        for (int i = 0; i < 8; ++i) {
            int r = rq * 8 + i;
            g_gtp4[q][r * G4 + ac] = acc[i][0] + comb[t][i];
        }
    }
}

// K4b: sum 12 partials per gate element, LSTM elementwise, reset g_best. 64x256.
__global__ void k_lstm() {
    const int idx = blockIdx.x * 256 + threadIdx.x;    // 0..16383 (b, j)
    if (blockIdx.x == 0 && threadIdx.x < 32) g_best[threadIdx.x] = 0ull;
    const int b = idx >> 9, j = idx & 511;
    float gv[4];
    #pragma unroll
    for (int g = 0; g < 4; ++g) {
        const int c = b * G4 + (g << 9) + j;
        float s = 0.f;
        #pragma unroll
        for (int q = 0; q < 4; ++q)
            s += g_g04[q][c] + g_g04[4 + q][c] + g_gtp4[q][c];
        gv[g] = s;
    }
    float ig = sigmoidf(gv[0]);
    float fg = sigmoidf(gv[1]);
    float gg = tanhf(gv[2]);
    float og = sigmoidf(gv[3]);
    float c = fg * g_c[idx] + ig * gg;
    g_c[idx] = c;
    g_h[idx] = og * tanhf(c);
}

__global__ void k_copyhc(float* __restrict__ hout, float* __restrict__ cout) {
    int idx = blockIdx.x * 256 + threadIdx.x;
    if (idx < BB * HH) __stcs(&hout[idx], g_h[idx]);
    else if (idx < 2 * BB * HH) __stcs(&cout[idx - BB * HH], g_c[idx - BB * HH]);
}

// ---------------------------------------------------------------------------
extern "C" void kernel_launch(void* const* d_in, const int* in_sizes, int n_in,
                              void* d_out, int out_size) {
    const float* feat   = (const float*)d_in[0];
    const float* emb    = (const float*)d_in[3];
    const float* W1_w   = (const float*)d_in[4];
    const float* W1_b   = (const float*)d_in[5];
    const float* W2_w   = (const float*)d_in[6];
    const float* W2_b   = (const float*)d_in[7];
    const float* Va_w   = (const float*)d_in[8];
    const float* Va_b   = (const float*)d_in[9];
    const float* Wih    = (const float*)d_in[10];
    const float* Whh    = (const float*)d_in[11];
    const float* bih    = (const float*)d_in[12];
    const float* bhh    = (const float*)d_in[13];
    const float* out_w  = (const float*)d_in[14];
    const float* out_b  = (const float*)d_in[15];
    const float* ihw    = (const float*)d_in[16];
    const float* ihb    = (const float*)d_in[17];
    const float* icw    = (const float*)d_in[18];
    const float* icb    = (const float*)d_in[19];
    const float* gate_w = (const float*)d_in[20];
    const float* gate_b = (const float*)d_in[21];

    float* out  = (float*)d_out;
    float* dec  = out;                                   // [B, T, V]
    float* hout = out + (size_t)BB * TT * VV;            // [B, H]
    float* cout = hout + (size_t)BB * HH;                // [B, H]
    float* attn = cout + (size_t)BB * HH;                // [B, T, P]

    k_mean<<<160, 256>>>(feat);
    k_inithc<<<16, 256>>>(ihw, ihb, icw, icb);
    k_encproj<<<dim3(8, 196), 256>>>(feat, W2_w, W2_b);

    for (int t = 0; t < TT; ++t) {
        const int nlog = (t == 0) ? 0 : NLOG;
        float* dec_prev = dec + (size_t)(t > 0 ? t - 1 : 0) * VV;
        k_fused1<<<nlog + 240, 256>>>(nlog, out_w, out_b, dec_prev,
                                      W1_w, W1_b, gate_w, gate_b, Whh, bih, bhh);
        k_fused2<<<352, 256>>>(Va_w, Va_b, emb, Wih);
        k_ctx<<<320, 512>>>(feat, attn + (size_t)t * PP);
        k_gates<<<256, 256>>>(Wih);
        k_lstm<<<64, 256>>>();
    }
    // tail: logits for the last step (no hprojA)
    k_fused1<<<NLOG, 256>>>(NLOG, out_w, out_b, dec + (size_t)(TT - 1) * VV,
                            W1_w, W1_b, gate_w, gate_b, Whh, bih, bhh);
    k_copyhc<<<128, 256>>>(hout, cout);
}